// round 13
// baseline (speedup 1.0000x reference)
#include <cuda_runtime.h>
#include <cuda_bf16.h>
#include <cuda_fp16.h>
#include <stdint.h>
#include <math.h>

#define NB 16
#define NTT 1024
#define NSS 1024
#define ND 768
#define NK3 1536

// ---------------------------------------------------------------------------
// scratch (static device globals — no allocations allowed)
// ---------------------------------------------------------------------------
__device__ float g_scores[(size_t)NB * NTT * NSS];         // G1 logits (fp32)
__device__ __half g_av_h[(size_t)NB * NTT * NSS];          // softmax result (fp16)
__device__ float g_gate[NB * NSS];
__device__ float g_gpart[8][NB * NSS];
__device__ float g_bias2[ND];
__device__ __nv_bfloat16 g_inp_hi[(size_t)NB * NTT * ND];  // GEMM1 A (3-term)
__device__ __nv_bfloat16 g_inp_lo[(size_t)NB * NTT * ND];
__device__ __nv_bfloat16 g_ctx_hi[(size_t)NB * NSS * ND];  // GEMM1 B (3-term)
__device__ __nv_bfloat16 g_ctx_lo[(size_t)NB * NSS * ND];
__device__ __half g_inp_h[(size_t)NB * NTT * ND];          // GEMM3 A part2
__device__ __half g_ctxT_h[(size_t)NB * ND * NSS];         // GEMM2 B
__device__ __half g_avg_h[(size_t)NB * NTT * NSS];         // GEMM2 A (av*gate)
__device__ __half g_cc_h[(size_t)NB * NTT * ND];           // GEMM3 A part1 (c*ws/1024)
__device__ __half g_w_h[ND * NK3];                         // GEMM3 B

// ---------------------------------------------------------------------------
// sm_80-compatible PTX helpers (NO tcgen05 — harness targets compute_103)
// ---------------------------------------------------------------------------
__device__ __forceinline__ uint32_t smem_to_u32(const void* p) {
    uint32_t a;
    asm("{ .reg .u64 t; cvta.to.shared.u64 t, %1; cvt.u32.u64 %0, t; }" : "=r"(a) : "l"(p));
    return a;
}

__device__ __forceinline__ void cpa16(uint32_t dst, const void* src) {
    asm volatile("cp.async.cg.shared.global [%0], [%1], 16;" :: "r"(dst), "l"(src));
}
#define CP_COMMIT() asm volatile("cp.async.commit_group;" ::: "memory")
#define CP_WAIT(n)  asm volatile("cp.async.wait_group %0;" :: "n"(n) : "memory")

__device__ __forceinline__ void ldsm4(uint32_t (&r)[4], uint32_t addr) {
    asm volatile("ldmatrix.sync.aligned.m8n8.x4.shared.b16 {%0,%1,%2,%3}, [%4];"
                 : "=r"(r[0]), "=r"(r[1]), "=r"(r[2]), "=r"(r[3]) : "r"(addr));
}

__device__ __forceinline__ void hmma_bf(float (&d)[4], const uint32_t (&a)[4],
                                        uint32_t b0, uint32_t b1) {
    asm volatile(
        "mma.sync.aligned.m16n8k16.row.col.f32.bf16.bf16.f32 "
        "{%0,%1,%2,%3}, {%4,%5,%6,%7}, {%8,%9}, {%0,%1,%2,%3};"
        : "+f"(d[0]), "+f"(d[1]), "+f"(d[2]), "+f"(d[3])
        : "r"(a[0]), "r"(a[1]), "r"(a[2]), "r"(a[3]), "r"(b0), "r"(b1));
}

__device__ __forceinline__ void hmma_f16(float (&d)[4], const uint32_t (&a)[4],
                                         uint32_t b0, uint32_t b1) {
    asm volatile(
        "mma.sync.aligned.m16n8k16.row.col.f32.f16.f16.f32 "
        "{%0,%1,%2,%3}, {%4,%5,%6,%7}, {%8,%9}, {%0,%1,%2,%3};"
        : "+f"(d[0]), "+f"(d[1]), "+f"(d[2]), "+f"(d[3])
        : "r"(a[0]), "r"(a[1]), "r"(a[2]), "r"(a[3]), "r"(b0), "r"(b1));
}

// byte offset of 16-bit elem (r, c) inside a SW64-swizzled tile (64B rows)
__device__ __forceinline__ uint32_t swz(int r, int c) {
    int off = (r << 6) + (c << 1);
    return (uint32_t)(off ^ ((off >> 3) & 0x30));
}

static constexpr int A_TB = 8192;   // 128x32 16-bit tile
static constexpr int B_TB = 4096;   // 64x32 16-bit tile

// ===========================================================================
// GEMM1: bf16 3-term split (AhBh + AhBl + AlBh), 128x64 tile, K-chunk 32
// scores[b] = inp[b] @ ctx[b]^T  (K=768) -> g_scores fp32
// 3-stage pipeline (wait -> sync -> prefetch -> compute), 2 CTAs/SM.
// grid (16, 8, NB) = 2048 CTAs -> 6.92 waves (tail ~1%)
// ===========================================================================
static constexpr int STG_G1  = 2 * A_TB + 2 * B_TB;  // 24 KB
static constexpr int SMEM_G1 = 3 * STG_G1;           // 72 KB -> 2 CTAs/SM

__device__ __forceinline__ void load_stage_g1(
    const __nv_bfloat16* __restrict__ ah, const __nv_bfloat16* __restrict__ al,
    const __nv_bfloat16* __restrict__ bh, const __nv_bfloat16* __restrict__ bl,
    int m0, int n0, int k0, uint32_t sbase)
{
    const int tid = threadIdx.x;
    #pragma unroll
    for (int j = 0; j < 2; ++j) {
        const int id = tid + 256 * j;
        const int r  = id >> 2;               // 0..127
        const int c  = (id & 3) << 3;
        const uint32_t off = swz(r, c);
        cpa16(sbase + off,        ah + (size_t)(m0 + r) * ND + k0 + c);
        cpa16(sbase + A_TB + off, al + (size_t)(m0 + r) * ND + k0 + c);
    }
    {
        const int r = tid >> 2;               // 0..63
        const int c = (tid & 3) << 3;
        const uint32_t off = swz(r, c);
        cpa16(sbase + 2 * A_TB + off,        bh + (size_t)(n0 + r) * ND + k0 + c);
        cpa16(sbase + 2 * A_TB + B_TB + off, bl + (size_t)(n0 + r) * ND + k0 + c);
    }
}

__global__ __launch_bounds__(256, 2)
void g1_gemm()
{
    extern __shared__ char smem[];
    const uint32_t sb = smem_to_u32(smem);
    const int tid = threadIdx.x;
    const int lane = tid & 31, wid = tid >> 5;
    const int rm = (wid & 3) * 32;     // warp row base (M)
    const int cn = (wid >> 2) * 32;    // warp col base (N), 0 or 32

    const int m0 = blockIdx.y * 128;
    const int n0 = blockIdx.x * 64;
    const int bz = blockIdx.z;

    const __nv_bfloat16* Ah = g_inp_hi + (size_t)bz * NTT * ND;
    const __nv_bfloat16* Al = g_inp_lo + (size_t)bz * NTT * ND;
    const __nv_bfloat16* Bh = g_ctx_hi + (size_t)bz * NSS * ND;
    const __nv_bfloat16* Bl = g_ctx_lo + (size_t)bz * NSS * ND;
    const int NC = ND / 32;

    float acc[2][4][4];
    #pragma unroll
    for (int i = 0; i < 2; ++i)
        #pragma unroll
        for (int j = 0; j < 4; ++j)
            #pragma unroll
            for (int v = 0; v < 4; ++v) acc[i][j][v] = 0.f;

    const int q = lane >> 3, l7 = lane & 7;
    const int ar = rm + ((q & 1) << 3) + l7;
    const int acq = (q >> 1) << 3;
    const int brq = ((q >> 1) << 3) + l7;
    const int bcq = (q & 1) << 3;

    load_stage_g1(Ah, Al, Bh, Bl, m0, n0, 0, sb);
    CP_COMMIT();
    load_stage_g1(Ah, Al, Bh, Bl, m0, n0, 32, sb + STG_G1);
    CP_COMMIT();

    int buf = 0;
    for (int kc = 0; kc < NC; ++kc) {
        if (kc + 1 < NC) { CP_WAIT(1); } else { CP_WAIT(0); }
        __syncthreads();
        if (kc + 2 < NC) {
            int nbuf = buf + 2; if (nbuf >= 3) nbuf -= 3;
            load_stage_g1(Ah, Al, Bh, Bl, m0, n0, (kc + 2) * 32,
                          sb + (uint32_t)nbuf * STG_G1);
            CP_COMMIT();
        }
        const uint32_t sbase = sb + (uint32_t)buf * STG_G1;
        #pragma unroll
        for (int k16 = 0; k16 < 2; ++k16) {
            const int kk = k16 * 16;
            uint32_t A0[4], A1[4], L0[4], L1[4];
            ldsm4(A0, sbase + swz(ar, kk + acq));
            ldsm4(A1, sbase + swz(ar + 16, kk + acq));
            ldsm4(L0, sbase + A_TB + swz(ar, kk + acq));
            ldsm4(L1, sbase + A_TB + swz(ar + 16, kk + acq));
            #pragma unroll
            for (int np = 0; np < 2; ++np) {
                uint32_t Bh4[4], Bl4[4];
                const uint32_t boff = swz(cn + np * 16 + brq, kk + bcq);
                ldsm4(Bh4, sbase + 2 * A_TB + boff);
                ldsm4(Bl4, sbase + 2 * A_TB + B_TB + boff);
                hmma_bf(acc[0][2 * np],     A0, Bh4[0], Bh4[1]);
                hmma_bf(acc[0][2 * np + 1], A0, Bh4[2], Bh4[3]);
                hmma_bf(acc[1][2 * np],     A1, Bh4[0], Bh4[1]);
                hmma_bf(acc[1][2 * np + 1], A1, Bh4[2], Bh4[3]);
                hmma_bf(acc[0][2 * np],     A0, Bl4[0], Bl4[1]);
                hmma_bf(acc[0][2 * np + 1], A0, Bl4[2], Bl4[3]);
                hmma_bf(acc[1][2 * np],     A1, Bl4[0], Bl4[1]);
                hmma_bf(acc[1][2 * np + 1], A1, Bl4[2], Bl4[3]);
                hmma_bf(acc[0][2 * np],     L0, Bh4[0], Bh4[1]);
                hmma_bf(acc[0][2 * np + 1], L0, Bh4[2], Bh4[3]);
                hmma_bf(acc[1][2 * np],     L1, Bh4[0], Bh4[1]);
                hmma_bf(acc[1][2 * np + 1], L1, Bh4[2], Bh4[3]);
            }
        }
        if (++buf == 3) buf = 0;
    }

    const int rbase = m0 + rm + (lane >> 2);
    const int cbase = n0 + cn + ((lane & 3) << 1);
    float* dst = g_scores + ((size_t)bz << 20);
    #pragma unroll
    for (int mt = 0; mt < 2; ++mt)
        #pragma unroll
        for (int h = 0; h < 2; ++h) {
            const int row = rbase + mt * 16 + h * 8;
            #pragma unroll
            for (int nt = 0; nt < 4; ++nt)
                *(float2*)(dst + (size_t)row * NSS + cbase + nt * 8) =
                    make_float2(acc[mt][nt][2 * h], acc[mt][nt][2 * h + 1]);
        }
}

// ===========================================================================
// 1-term fp16 GEMM, 128x64 tile, K-chunk 32, 4-stage early-prefetch pipeline
//   MODE 0: c' = avg @ ctxT^T (K=1024) -> cc_h = fp16(c' * ws / 1024)
//   MODE 1: h = [cc;inp_h] @ w_h^T + bias2, PReLU -> out1 [T,B,D]
// grid 1536 CTAs -> 5.19 waves (tail ~4%)
// ===========================================================================
static constexpr int STG_1T  = A_TB + B_TB;   // 12 KB
static constexpr int SMEM_1T = 4 * STG_1T;    // 48 KB -> 2 CTAs/SM

__device__ __forceinline__ void load_stage_1t(
    const __half* __restrict__ a, const __half* __restrict__ b,
    int lda, int ldb, int m0, int n0, int ka, int kb, uint32_t sbase)
{
    const int tid = threadIdx.x;
    #pragma unroll
    for (int j = 0; j < 2; ++j) {
        const int id = tid + 256 * j;
        const int r  = id >> 2;
        const int c  = (id & 3) << 3;
        cpa16(sbase + swz(r, c), a + (size_t)(m0 + r) * lda + ka + c);
    }
    {
        const int r = tid >> 2;
        const int c = (tid & 3) << 3;
        cpa16(sbase + A_TB + swz(r, c), b + (size_t)(n0 + r) * ldb + kb + c);
    }
}

template <int MODE>
__global__ __launch_bounds__(256, 2)
void gemm_1t(const float* __restrict__ wsp, const float* __restrict__ pap,
             float* __restrict__ out1)
{
    extern __shared__ char smem[];
    const uint32_t sb = smem_to_u32(smem);
    const int tid = threadIdx.x;
    const int lane = tid & 31, wid = tid >> 5;
    const int rm = (wid & 3) * 32;
    const int cn = (wid >> 2) * 32;

    const int m0 = blockIdx.y * 128;
    const int n0 = blockIdx.x * 64;
    const int bz = blockIdx.z;

    int K, lda, ldb;
    const __half *A, *B;
    if (MODE == 0) {
        K = NSS; lda = NSS; ldb = NSS;
        A = g_avg_h + (size_t)bz * NTT * NSS;
        B = g_ctxT_h + (size_t)bz * ND * NSS;
    } else {
        K = NK3; lda = ND; ldb = NK3;
        A = g_cc_h;
        B = g_w_h;
    }
    const int NC = K / 32;

    float acc[2][4][4];
    #pragma unroll
    for (int i = 0; i < 2; ++i)
        #pragma unroll
        for (int j = 0; j < 4; ++j)
            #pragma unroll
            for (int v = 0; v < 4; ++v) acc[i][j][v] = 0.f;

    const int q = lane >> 3, l7 = lane & 7;
    const int ar = rm + ((q & 1) << 3) + l7;
    const int acq = (q >> 1) << 3;
    const int brq = ((q >> 1) << 3) + l7;
    const int bcq = (q & 1) << 3;

    load_stage_1t(A, B, lda, ldb, m0, n0, 0, 0, sb);
    CP_COMMIT();
    load_stage_1t(A, B, lda, ldb, m0, n0, 32, 32, sb + STG_1T);
    CP_COMMIT();

    for (int kc = 0; kc < NC; ++kc) {
        if (kc + 2 < NC) {
            const __half* a = A;
            int ka = (kc + 2) * 32;
            const int kb = ka;
            if (MODE == 1 && ka >= ND) { a = g_inp_h; ka -= ND; }
            load_stage_1t(a, B, lda, ldb, m0, n0, ka, kb,
                          sb + (uint32_t)((kc + 2) & 3) * STG_1T);
            CP_COMMIT();
            CP_WAIT(2);
        } else if (kc + 1 < NC) {
            CP_WAIT(1);
        } else {
            CP_WAIT(0);
        }
        __syncthreads();

        const uint32_t sbase = sb + (uint32_t)(kc & 3) * STG_1T;
        #pragma unroll
        for (int k16 = 0; k16 < 2; ++k16) {
            const int kk = k16 * 16;
            uint32_t A0[4], A1[4];
            ldsm4(A0, sbase + swz(ar, kk + acq));
            ldsm4(A1, sbase + swz(ar + 16, kk + acq));
            #pragma unroll
            for (int np = 0; np < 2; ++np) {
                uint32_t B4[4];
                ldsm4(B4, sbase + A_TB + swz(cn + np * 16 + brq, kk + bcq));
                hmma_f16(acc[0][2 * np],     A0, B4[0], B4[1]);
                hmma_f16(acc[0][2 * np + 1], A0, B4[2], B4[3]);
                hmma_f16(acc[1][2 * np],     A1, B4[0], B4[1]);
                hmma_f16(acc[1][2 * np + 1], A1, B4[2], B4[3]);
            }
        }
    }

    const int rbase = m0 + rm + (lane >> 2);
    const int cbase = n0 + cn + ((lane & 3) << 1);

    if (MODE == 0) {
        const float sc = __ldg(wsp) * (1.0f / 1024.0f);
        #pragma unroll
        for (int mt = 0; mt < 2; ++mt)
            #pragma unroll
            for (int h = 0; h < 2; ++h) {
                const int row = rbase + mt * 16 + h * 8;
                __half* dst = g_cc_h + ((size_t)bz * NTT + row) * ND;
                #pragma unroll
                for (int nt = 0; nt < 4; ++nt) {
                    const int col = cbase + nt * 8;
                    *(__half2*)(dst + col) = __floats2half2_rn(
                        acc[mt][nt][2 * h] * sc, acc[mt][nt][2 * h + 1] * sc);
                }
            }
    } else {
        const float pa = __ldg(pap);
        #pragma unroll
        for (int mt = 0; mt < 2; ++mt)
            #pragma unroll
            for (int h = 0; h < 2; ++h) {
                const int row = rbase + mt * 16 + h * 8;
                const int bb = row >> 10, tt = row & 1023;
                float* dst = out1 + ((size_t)tt * NB + bb) * ND;
                #pragma unroll
                for (int nt = 0; nt < 4; ++nt) {
                    const int col = cbase + nt * 8;
                    float v0 = acc[mt][nt][2 * h]     + __ldg(&g_bias2[col]);
                    float v1 = acc[mt][nt][2 * h + 1] + __ldg(&g_bias2[col + 1]);
                    v0 = (v0 >= 0.f) ? v0 : pa * v0;
                    v1 = (v1 >= 0.f) ? v1 : pa * v1;
                    *(float2*)(dst + col) = make_float2(v0, v1);
                }
            }
    }
}

// ---------------------------------------------------------------------------
// fused inp prep: fp32 -> bf16 hi/lo + fp16 (one read of inp)
// ---------------------------------------------------------------------------
__global__ __launch_bounds__(256)
void fuse_inp(const float* __restrict__ src)
{
    const size_t i = (size_t)blockIdx.x * 256 + threadIdx.x;
    float4 v = ((const float4*)src)[i];
    __nv_bfloat16 h0 = __float2bfloat16(v.x), h1 = __float2bfloat16(v.y);
    __nv_bfloat16 h2 = __float2bfloat16(v.z), h3 = __float2bfloat16(v.w);
    __nv_bfloat16 l0 = __float2bfloat16(v.x - __bfloat162float(h0));
    __nv_bfloat16 l1 = __float2bfloat16(v.y - __bfloat162float(h1));
    __nv_bfloat16 l2 = __float2bfloat16(v.z - __bfloat162float(h2));
    __nv_bfloat16 l3 = __float2bfloat16(v.w - __bfloat162float(h3));
    ((__nv_bfloat162*)g_inp_hi)[2 * i]     = __halves2bfloat162(h0, h1);
    ((__nv_bfloat162*)g_inp_hi)[2 * i + 1] = __halves2bfloat162(h2, h3);
    ((__nv_bfloat162*)g_inp_lo)[2 * i]     = __halves2bfloat162(l0, l1);
    ((__nv_bfloat162*)g_inp_lo)[2 * i + 1] = __halves2bfloat162(l2, l3);
    ((__half2*)g_inp_h)[2 * i]     = __floats2half2_rn(v.x, v.y);
    ((__half2*)g_inp_h)[2 * i + 1] = __floats2half2_rn(v.z, v.w);
}

// ---------------------------------------------------------------------------
// fused ctx prep: one read of ctx -> bf16 hi/lo (row-major) + fp16 transpose
// ---------------------------------------------------------------------------
__global__ __launch_bounds__(256)
void fuse_ctx(const float* __restrict__ ctx)
{
    __shared__ float ts[64][33];
    const int b = blockIdx.z;
    const int d0 = blockIdx.x * 32;
    const int s0 = blockIdx.y * 64;
    const int tx = threadIdx.x, ty = threadIdx.y;   // 32 x 8
    #pragma unroll
    for (int r = ty; r < 64; r += 8) {
        const float v = ctx[(size_t)b * NSS * ND + (size_t)(s0 + r) * ND + d0 + tx];
        ts[r][tx] = v;
        const __nv_bfloat16 h = __float2bfloat16(v);
        const __nv_bfloat16 l = __float2bfloat16(v - __bfloat162float(h));
        const size_t o = ((size_t)b * NSS + s0 + r) * ND + d0 + tx;
        g_ctx_hi[o] = h;
        g_ctx_lo[o] = l;
    }
    __syncthreads();
    #pragma unroll
    for (int r = ty; r < 32; r += 8) {
        float v0 = ts[2 * tx][r];
        float v1 = ts[2 * tx + 1][r];
        const size_t o = (size_t)b * ND * NSS + (size_t)(d0 + r) * NSS + s0 + 2 * tx;
        *(__half2*)(g_ctxT_h + o) = __floats2half2_rn(v0, v1);
    }
}

// ---------------------------------------------------------------------------
// W prep: W -> fp16, bias2[n] = bs * sum_{k<768} W[n,k] + b_out[n]
// ---------------------------------------------------------------------------
__global__ __launch_bounds__(256)
void wprep(const float* __restrict__ W, const float* __restrict__ bo,
           const float* __restrict__ bsp)
{
    const int n = blockIdx.x;
    const int tid = threadIdx.x;
    float sum = 0.f;
    #pragma unroll
    for (int k0 = 0; k0 < NK3; k0 += 1024) {
        const int k = k0 + tid * 4;
        float4 v = *(const float4*)(W + (size_t)n * NK3 + k);
        ((__half2*)(g_w_h + (size_t)n * NK3 + k))[0] = __floats2half2_rn(v.x, v.y);
        ((__half2*)(g_w_h + (size_t)n * NK3 + k))[1] = __floats2half2_rn(v.z, v.w);
        if (k < ND) sum += (v.x + v.y) + (v.z + v.w);
    }
    __shared__ float red[8];
    #pragma unroll
    for (int o = 16; o; o >>= 1) sum += __shfl_xor_sync(0xffffffffu, sum, o);
    if ((tid & 31) == 0) red[tid >> 5] = sum;
    __syncthreads();
    if (tid == 0) {
        float t = ((red[0] + red[1]) + (red[2] + red[3])) +
                  ((red[4] + red[5]) + (red[6] + red[7]));
        g_bias2[n] = __ldg(bsp) * t + __ldg(bo + n);
    }
}

// ---------------------------------------------------------------------------
// row softmax over S: reads fp32 logits, writes fp16 av to g_av_h
// ---------------------------------------------------------------------------
__global__ __launch_bounds__(256)
void softmax_k()
{
    const float* row = g_scores + (size_t)blockIdx.x * NSS;
    const int tid = threadIdx.x;
    const unsigned FULL = 0xffffffffu;
    float4 x = *(const float4*)(row + tid * 4);
    float m = fmaxf(fmaxf(x.x, x.y), fmaxf(x.z, x.w));
    __shared__ float sred[8];
    __shared__ float sred2[8];
    #pragma unroll
    for (int o = 16; o; o >>= 1) m = fmaxf(m, __shfl_xor_sync(FULL, m, o));
    if ((tid & 31) == 0) sred[tid >> 5] = m;
    __syncthreads();
    m = fmaxf(fmaxf(fmaxf(sred[0], sred[1]), fmaxf(sred[2], sred[3])),
              fmaxf(fmaxf(sred[4], sred[5]), fmaxf(sred[6], sred[7])));
    float e0 = expf(x.x - m), e1 = expf(x.y - m), e2 = expf(x.z - m), e3 = expf(x.w - m);
    float s = (e0 + e1) + (e2 + e3);
    #pragma unroll
    for (int o = 16; o; o >>= 1) s += __shfl_xor_sync(FULL, s, o);
    if ((tid & 31) == 0) sred2[tid >> 5] = s;
    __syncthreads();
    s = ((sred2[0] + sred2[1]) + (sred2[2] + sred2[3])) +
        ((sred2[4] + sred2[5]) + (sred2[6] + sred2[7]));
    const float inv = 1.0f / s;
    __half* dst = g_av_h + (size_t)blockIdx.x * NSS + tid * 4;
    *(__half2*)(dst)     = __floats2half2_rn(e0 * inv, e1 * inv);
    *(__half2*)(dst + 2) = __floats2half2_rn(e2 * inv, e3 * inv);
}

// ---------------------------------------------------------------------------
// gate, phase 1: partial column sums over 128-row chunks (fp16 input)
// ---------------------------------------------------------------------------
__global__ __launch_bounds__(256)
void gate_part()
{
    const int s2 = blockIdx.x * 512 + threadIdx.x * 2;
    const int tc = blockIdx.y;
    const int b = blockIdx.z;
    const __half* p = g_av_h + (size_t)b * NTT * NSS + (size_t)tc * 128 * NSS + s2;
    float2 a0 = {0.f, 0.f}, a1 = {0.f, 0.f}, a2 = {0.f, 0.f}, a3 = {0.f, 0.f};
    #pragma unroll
    for (int t = 0; t < 128; t += 4) {
        float2 f0 = __half22float2(*(const __half2*)(p + (size_t)(t + 0) * NSS));
        float2 f1 = __half22float2(*(const __half2*)(p + (size_t)(t + 1) * NSS));
        float2 f2 = __half22float2(*(const __half2*)(p + (size_t)(t + 2) * NSS));
        float2 f3 = __half22float2(*(const __half2*)(p + (size_t)(t + 3) * NSS));
        a0.x += f0.x; a0.y += f0.y;
        a1.x += f1.x; a1.y += f1.y;
        a2.x += f2.x; a2.y += f2.y;
        a3.x += f3.x; a3.y += f3.y;
    }
    float2 r;
    r.x = (a0.x + a1.x) + (a2.x + a3.x);
    r.y = (a0.y + a1.y) + (a2.y + a3.y);
    *(float2*)(&g_gpart[tc][b * NSS + s2]) = r;
}

// gate, phase 2: reduce 8 partials + sigmoid
__global__ __launch_bounds__(256)
void gate_fin()
{
    const int gid = blockIdx.x * 256 + threadIdx.x;
    float s = 0.f;
    #pragma unroll
    for (int i = 0; i < 8; ++i) s += g_gpart[i][gid];
    g_gate[gid] = 1.0f / (1.0f + expf(-s));
}

// ---------------------------------------------------------------------------
// av_g: reads fp16 av; out2 [T,B,S] = av*gate/1024 (fp32);
//       g_avg_h [B,T,S] = fp16(av*gate)
// ---------------------------------------------------------------------------
__global__ __launch_bounds__(256)
void avg_k(float* __restrict__ out2)
{
    const int bt = blockIdx.x;
    const int b = bt >> 10, t = bt & 1023;
    const int s = threadIdx.x * 4;
    const __half* src = g_av_h + (size_t)bt * NSS + s;
    float2 f01 = __half22float2(*(const __half2*)(src));
    float2 f23 = __half22float2(*(const __half2*)(src + 2));
    float4 g = *(const float4*)(g_gate + b * NSS + s);
    float4 v;
    v.x = f01.x * g.x; v.y = f01.y * g.y; v.z = f23.x * g.z; v.w = f23.y * g.w;
    const float pool = 1.0f / 1024.0f;
    *(float4*)(out2 + ((size_t)t * NB + b) * NSS + s) =
        make_float4(v.x * pool, v.y * pool, v.z * pool, v.w * pool);
    __half2* ph = (__half2*)(g_avg_h + (size_t)bt * NSS + s);
    ph[0] = __floats2half2_rn(v.x, v.y);
    ph[1] = __floats2half2_rn(v.z, v.w);
}

// ---------------------------------------------------------------------------
extern "C" void kernel_launch(void* const* d_in, const int* in_sizes, int n_in,
                              void* d_out, int out_size)
{
    const float* inp = (const float*)d_in[0];   // [B,T,768]
    const float* ctx = (const float*)d_in[1];   // [B,S,768]
    const float* W   = (const float*)d_in[2];   // [768,1536]
    const float* bo  = (const float*)d_in[3];   // [768]
    const float* ws  = (const float*)d_in[4];   // [1]
    const float* bs  = (const float*)d_in[5];   // [1]
    const float* pa  = (const float*)d_in[6];   // [1]
    float* out1 = (float*)d_out;                          // attn_h^T [T,B,768]
    float* out2 = out1 + (size_t)NTT * NB * ND;           // av_g^T   [T,B,S]

    cudaFuncSetAttribute(g1_gemm, cudaFuncAttributeMaxDynamicSharedMemorySize, SMEM_G1);
    cudaFuncSetAttribute(gemm_1t<0>, cudaFuncAttributeMaxDynamicSharedMemorySize, SMEM_1T);
    cudaFuncSetAttribute(gemm_1t<1>, cudaFuncAttributeMaxDynamicSharedMemorySize, SMEM_1T);

    fuse_inp<<<NB * NTT * ND / 4 / 256, 256>>>(inp);
    fuse_ctx<<<dim3(ND / 32, NSS / 64, NB), dim3(32, 8)>>>(ctx);
    wprep<<<ND, 256>>>(W, bo, bs);

    g1_gemm<<<dim3(16, 8, NB), 256, SMEM_G1>>>();
    softmax_k<<<NB * NTT, 256>>>();
    gate_part<<<dim3(2, 8, NB), 256>>>();
    gate_fin<<<NB * NSS / 256, 256>>>();
    avg_k<<<NB * NTT, 256>>>(out2);
    gemm_1t<0><<<dim3(12, 8, NB), 256, SMEM_1T>>>(ws, pa, out1);
    gemm_1t<1><<<dim3(12, 128, 1), 256, SMEM_1T>>>(ws, pa, out1);
}

// round 14
// speedup vs baseline: 1.1186x; 1.1186x over previous
#include <cuda_runtime.h>
#include <cuda_bf16.h>
#include <cuda_fp16.h>
#include <stdint.h>
#include <math.h>

#define NB 16
#define NTT 1024
#define NSS 1024
#define ND 768
#define NK3 1536

// ---------------------------------------------------------------------------
// scratch (static device globals — no allocations allowed)
// ---------------------------------------------------------------------------
__device__ float g_scores[(size_t)NB * NTT * NSS];         // G1 logits (fp32)
__device__ __half g_av_h[(size_t)NB * NTT * NSS];          // softmax result (fp16)
__device__ float g_gate[NB * NSS];
__device__ float g_gpart[8][NB * NSS];
__device__ float g_bias2[ND];
__device__ __nv_bfloat16 g_inp_hi[(size_t)NB * NTT * ND];  // GEMM1 A (3-term)
__device__ __nv_bfloat16 g_inp_lo[(size_t)NB * NTT * ND];
__device__ __nv_bfloat16 g_ctx_hi[(size_t)NB * NSS * ND];  // GEMM1 B (3-term)
__device__ __nv_bfloat16 g_ctx_lo[(size_t)NB * NSS * ND];
__device__ __half g_inp_h[(size_t)NB * NTT * ND];          // GEMM3 A part2
__device__ __half g_ctxT_h[(size_t)NB * ND * NSS];         // GEMM2 B
__device__ __half g_avg_h[(size_t)NB * NTT * NSS];         // GEMM2 A (av*gate)
__device__ __half g_cc_h[(size_t)NB * NTT * ND];           // GEMM3 A part1 (c*ws/1024)
__device__ __half g_w_h[ND * NK3];                         // GEMM3 B

// ---------------------------------------------------------------------------
// sm_80-compatible PTX helpers (NO tcgen05 — harness targets compute_103)
// ---------------------------------------------------------------------------
__device__ __forceinline__ uint32_t smem_to_u32(const void* p) {
    uint32_t a;
    asm("{ .reg .u64 t; cvta.to.shared.u64 t, %1; cvt.u32.u64 %0, t; }" : "=r"(a) : "l"(p));
    return a;
}

__device__ __forceinline__ void cpa16(uint32_t dst, const void* src) {
    asm volatile("cp.async.cg.shared.global [%0], [%1], 16;" :: "r"(dst), "l"(src));
}
#define CP_COMMIT() asm volatile("cp.async.commit_group;" ::: "memory")
#define CP_WAIT(n)  asm volatile("cp.async.wait_group %0;" :: "n"(n) : "memory")

__device__ __forceinline__ void ldsm4(uint32_t (&r)[4], uint32_t addr) {
    asm volatile("ldmatrix.sync.aligned.m8n8.x4.shared.b16 {%0,%1,%2,%3}, [%4];"
                 : "=r"(r[0]), "=r"(r[1]), "=r"(r[2]), "=r"(r[3]) : "r"(addr));
}

__device__ __forceinline__ void hmma_bf(float (&d)[4], const uint32_t (&a)[4],
                                        uint32_t b0, uint32_t b1) {
    asm volatile(
        "mma.sync.aligned.m16n8k16.row.col.f32.bf16.bf16.f32 "
        "{%0,%1,%2,%3}, {%4,%5,%6,%7}, {%8,%9}, {%0,%1,%2,%3};"
        : "+f"(d[0]), "+f"(d[1]), "+f"(d[2]), "+f"(d[3])
        : "r"(a[0]), "r"(a[1]), "r"(a[2]), "r"(a[3]), "r"(b0), "r"(b1));
}

__device__ __forceinline__ void hmma_f16(float (&d)[4], const uint32_t (&a)[4],
                                         uint32_t b0, uint32_t b1) {
    asm volatile(
        "mma.sync.aligned.m16n8k16.row.col.f32.f16.f16.f32 "
        "{%0,%1,%2,%3}, {%4,%5,%6,%7}, {%8,%9}, {%0,%1,%2,%3};"
        : "+f"(d[0]), "+f"(d[1]), "+f"(d[2]), "+f"(d[3])
        : "r"(a[0]), "r"(a[1]), "r"(a[2]), "r"(a[3]), "r"(b0), "r"(b1));
}

// byte offset of 16-bit elem (r, c) inside a 128x32 SW64-swizzled tile (64B rows)
__device__ __forceinline__ uint32_t swz(int r, int c) {
    int off = (r << 6) + (c << 1);
    return (uint32_t)(off ^ ((off >> 3) & 0x30));
}

// ===========================================================================
// GEMM1: bf16 3-term split (AhBh + AhBl + AlBh), 128x128 tile, K-chunk 32
// 3-stage pipeline (wait -> sync -> prefetch -> compute), 2 CTAs/SM.  [R10]
// ===========================================================================
static constexpr int TILE_B   = 8192;        // one 128x32 16-bit tile (SW64)
static constexpr int STAGE_B  = 4 * TILE_B;  // Ah, Al, Bh, Bl = 32 KB
static constexpr int SMEM_G1  = 3 * STAGE_B; // 96 KB -> 2 CTAs/SM

__device__ __forceinline__ void load_stage_g1(
    const __nv_bfloat16* __restrict__ ah, const __nv_bfloat16* __restrict__ al,
    const __nv_bfloat16* __restrict__ bh, const __nv_bfloat16* __restrict__ bl,
    int m0, int n0, int k0, uint32_t sbase)
{
    const int tid = threadIdx.x;
    #pragma unroll
    for (int j = 0; j < 2; ++j) {
        const int id = tid + 256 * j;
        const int r  = id >> 2;
        const int c  = (id & 3) << 3;
        const uint32_t off = swz(r, c);
        cpa16(sbase + off,              ah + (size_t)(m0 + r) * ND + k0 + c);
        cpa16(sbase + TILE_B + off,     al + (size_t)(m0 + r) * ND + k0 + c);
        cpa16(sbase + 2 * TILE_B + off, bh + (size_t)(n0 + r) * ND + k0 + c);
        cpa16(sbase + 3 * TILE_B + off, bl + (size_t)(n0 + r) * ND + k0 + c);
    }
}

__global__ __launch_bounds__(256, 2)
void g1_gemm()
{
    extern __shared__ char smem[];
    const uint32_t sb = smem_to_u32(smem);
    const int tid = threadIdx.x;
    const int lane = tid & 31, wid = tid >> 5;
    const int rm = (wid & 3) * 32;
    const int cn = (wid >> 2) * 64;

    const int m0 = blockIdx.y * 128;
    const int n0 = blockIdx.x * 128;
    const int bz = blockIdx.z;

    const __nv_bfloat16* Ah = g_inp_hi + (size_t)bz * NTT * ND;
    const __nv_bfloat16* Al = g_inp_lo + (size_t)bz * NTT * ND;
    const __nv_bfloat16* Bh = g_ctx_hi + (size_t)bz * NSS * ND;
    const __nv_bfloat16* Bl = g_ctx_lo + (size_t)bz * NSS * ND;
    const int NC = ND / 32;

    float acc[2][8][4];
    #pragma unroll
    for (int i = 0; i < 2; ++i)
        #pragma unroll
        for (int j = 0; j < 8; ++j)
            #pragma unroll
            for (int v = 0; v < 4; ++v) acc[i][j][v] = 0.f;

    const int q = lane >> 3, l7 = lane & 7;
    const int ar = rm + ((q & 1) << 3) + l7;
    const int acq = (q >> 1) << 3;
    const int brq = ((q >> 1) << 3) + l7;
    const int bcq = (q & 1) << 3;

    load_stage_g1(Ah, Al, Bh, Bl, m0, n0, 0, sb);
    CP_COMMIT();
    load_stage_g1(Ah, Al, Bh, Bl, m0, n0, 32, sb + STAGE_B);
    CP_COMMIT();

    int buf = 0;
    for (int kc = 0; kc < NC; ++kc) {
        if (kc + 1 < NC) { CP_WAIT(1); } else { CP_WAIT(0); }
        __syncthreads();
        if (kc + 2 < NC) {
            int nbuf = buf + 2; if (nbuf >= 3) nbuf -= 3;
            load_stage_g1(Ah, Al, Bh, Bl, m0, n0, (kc + 2) * 32,
                          sb + (uint32_t)nbuf * STAGE_B);
            CP_COMMIT();
        }
        const uint32_t sbase = sb + (uint32_t)buf * STAGE_B;
        #pragma unroll
        for (int k16 = 0; k16 < 2; ++k16) {
            const int kk = k16 * 16;
            uint32_t A0[4], A1[4], L0[4], L1[4];
            ldsm4(A0, sbase + swz(ar, kk + acq));
            ldsm4(A1, sbase + swz(ar + 16, kk + acq));
            ldsm4(L0, sbase + TILE_B + swz(ar, kk + acq));
            ldsm4(L1, sbase + TILE_B + swz(ar + 16, kk + acq));
            #pragma unroll
            for (int np = 0; np < 4; ++np) {
                uint32_t Bh4[4], Bl4[4];
                const uint32_t boff = swz(cn + np * 16 + brq, kk + bcq);
                ldsm4(Bh4, sbase + 2 * TILE_B + boff);
                ldsm4(Bl4, sbase + 3 * TILE_B + boff);
                hmma_bf(acc[0][2 * np],     A0, Bh4[0], Bh4[1]);
                hmma_bf(acc[0][2 * np + 1], A0, Bh4[2], Bh4[3]);
                hmma_bf(acc[1][2 * np],     A1, Bh4[0], Bh4[1]);
                hmma_bf(acc[1][2 * np + 1], A1, Bh4[2], Bh4[3]);
                hmma_bf(acc[0][2 * np],     A0, Bl4[0], Bl4[1]);
                hmma_bf(acc[0][2 * np + 1], A0, Bl4[2], Bl4[3]);
                hmma_bf(acc[1][2 * np],     A1, Bl4[0], Bl4[1]);
                hmma_bf(acc[1][2 * np + 1], A1, Bl4[2], Bl4[3]);
                hmma_bf(acc[0][2 * np],     L0, Bh4[0], Bh4[1]);
                hmma_bf(acc[0][2 * np + 1], L0, Bh4[2], Bh4[3]);
                hmma_bf(acc[1][2 * np],     L1, Bh4[0], Bh4[1]);
                hmma_bf(acc[1][2 * np + 1], L1, Bh4[2], Bh4[3]);
            }
        }
        if (++buf == 3) buf = 0;
    }

    const int rbase = m0 + rm + (lane >> 2);
    const int cbase = n0 + cn + ((lane & 3) << 1);
    float* dst = g_scores + ((size_t)bz << 20);
    #pragma unroll
    for (int mt = 0; mt < 2; ++mt)
        #pragma unroll
        for (int h = 0; h < 2; ++h) {
            const int row = rbase + mt * 16 + h * 8;
            #pragma unroll
            for (int nt = 0; nt < 8; ++nt)
                *(float2*)(dst + (size_t)row * NSS + cbase + nt * 8) =
                    make_float2(acc[mt][nt][2 * h], acc[mt][nt][2 * h + 1]);
        }
}

// ===========================================================================
// 1-term fp16 GEMM, 128x128 tile, K-chunk 32, 4-stage early-prefetch  [R10]
// ===========================================================================
static constexpr int STG1T   = 2 * TILE_B;      // A + B = 16 KB
static constexpr int SMEM_1T = 4 * STG1T;       // 64 KB -> 2 CTAs/SM

__device__ __forceinline__ void load_stage_1t(
    const __half* __restrict__ a, const __half* __restrict__ b,
    int lda, int ldb, int m0, int n0, int ka, int kb, uint32_t sbase)
{
    const int tid = threadIdx.x;
    #pragma unroll
    for (int j = 0; j < 2; ++j) {
        const int id = tid + 256 * j;
        const int r  = id >> 2;
        const int c  = (id & 3) << 3;
        const uint32_t off = swz(r, c);
        cpa16(sbase + off,          a + (size_t)(m0 + r) * lda + ka + c);
        cpa16(sbase + TILE_B + off, b + (size_t)(n0 + r) * ldb + kb + c);
    }
}

template <int MODE>
__global__ __launch_bounds__(256, 2)
void gemm_1t(const float* __restrict__ wsp, const float* __restrict__ pap,
             float* __restrict__ out1)
{
    extern __shared__ char smem[];
    const uint32_t sb = smem_to_u32(smem);
    const int tid = threadIdx.x;
    const int lane = tid & 31, wid = tid >> 5;
    const int rm = (wid & 3) * 32;
    const int cn = (wid >> 2) * 64;

    const int m0 = blockIdx.y * 128;
    const int n0 = blockIdx.x * 128;
    const int bz = blockIdx.z;

    int K, lda, ldb;
    const __half *A, *B;
    if (MODE == 0) {
        K = NSS; lda = NSS; ldb = NSS;
        A = g_avg_h + (size_t)bz * NTT * NSS;
        B = g_ctxT_h + (size_t)bz * ND * NSS;
    } else {
        K = NK3; lda = ND; ldb = NK3;
        A = g_cc_h;
        B = g_w_h;
    }
    const int NC = K / 32;

    float acc[2][8][4];
    #pragma unroll
    for (int i = 0; i < 2; ++i)
        #pragma unroll
        for (int j = 0; j < 8; ++j)
            #pragma unroll
            for (int v = 0; v < 4; ++v) acc[i][j][v] = 0.f;

    const int q = lane >> 3, l7 = lane & 7;
    const int ar = rm + ((q & 1) << 3) + l7;
    const int acq = (q >> 1) << 3;
    const int brq = ((q >> 1) << 3) + l7;
    const int bcq = (q & 1) << 3;

    load_stage_1t(A, B, lda, ldb, m0, n0, 0, 0, sb);
    CP_COMMIT();
    load_stage_1t(A, B, lda, ldb, m0, n0, 32, 32, sb + STG1T);
    CP_COMMIT();

    for (int kc = 0; kc < NC; ++kc) {
        if (kc + 2 < NC) {
            const __half* a = A;
            int ka = (kc + 2) * 32;
            const int kb = ka;
            if (MODE == 1 && ka >= ND) { a = g_inp_h; ka -= ND; }
            load_stage_1t(a, B, lda, ldb, m0, n0, ka, kb,
                          sb + (uint32_t)((kc + 2) & 3) * STG1T);
            CP_COMMIT();
            CP_WAIT(2);
        } else if (kc + 1 < NC) {
            CP_WAIT(1);
        } else {
            CP_WAIT(0);
        }
        __syncthreads();

        const uint32_t sbase = sb + (uint32_t)(kc & 3) * STG1T;
        #pragma unroll
        for (int k16 = 0; k16 < 2; ++k16) {
            const int kk = k16 * 16;
            uint32_t A0[4], A1[4];
            ldsm4(A0, sbase + swz(ar, kk + acq));
            ldsm4(A1, sbase + swz(ar + 16, kk + acq));
            #pragma unroll
            for (int np = 0; np < 4; ++np) {
                uint32_t B4[4];
                ldsm4(B4, sbase + TILE_B + swz(cn + np * 16 + brq, kk + bcq));
                hmma_f16(acc[0][2 * np],     A0, B4[0], B4[1]);
                hmma_f16(acc[0][2 * np + 1], A0, B4[2], B4[3]);
                hmma_f16(acc[1][2 * np],     A1, B4[0], B4[1]);
                hmma_f16(acc[1][2 * np + 1], A1, B4[2], B4[3]);
            }
        }
    }

    const int rbase = m0 + rm + (lane >> 2);
    const int cbase = n0 + cn + ((lane & 3) << 1);

    if (MODE == 0) {
        const float sc = __ldg(wsp) * (1.0f / 1024.0f);
        #pragma unroll
        for (int mt = 0; mt < 2; ++mt)
            #pragma unroll
            for (int h = 0; h < 2; ++h) {
                const int row = rbase + mt * 16 + h * 8;
                __half* dst = g_cc_h + ((size_t)bz * NTT + row) * ND;
                #pragma unroll
                for (int nt = 0; nt < 8; ++nt) {
                    const int col = cbase + nt * 8;
                    *(__half2*)(dst + col) = __floats2half2_rn(
                        acc[mt][nt][2 * h] * sc, acc[mt][nt][2 * h + 1] * sc);
                }
            }
    } else {
        const float pa = __ldg(pap);
        #pragma unroll
        for (int mt = 0; mt < 2; ++mt)
            #pragma unroll
            for (int h = 0; h < 2; ++h) {
                const int row = rbase + mt * 16 + h * 8;
                const int bb = row >> 10, tt = row & 1023;
                float* dst = out1 + ((size_t)tt * NB + bb) * ND;
                #pragma unroll
                for (int nt = 0; nt < 8; ++nt) {
                    const int col = cbase + nt * 8;
                    float v0 = acc[mt][nt][2 * h]     + __ldg(&g_bias2[col]);
                    float v1 = acc[mt][nt][2 * h + 1] + __ldg(&g_bias2[col + 1]);
                    v0 = (v0 >= 0.f) ? v0 : pa * v0;
                    v1 = (v1 >= 0.f) ? v1 : pa * v1;
                    *(float2*)(dst + col) = make_float2(v0, v1);
                }
            }
    }
}

// ---------------------------------------------------------------------------
// fused inp prep: fp32 -> bf16 hi/lo + fp16 (one read of inp)
// ---------------------------------------------------------------------------
__global__ __launch_bounds__(256)
void fuse_inp(const float* __restrict__ src)
{
    const size_t i = (size_t)blockIdx.x * 256 + threadIdx.x;
    float4 v = ((const float4*)src)[i];
    __nv_bfloat16 h0 = __float2bfloat16(v.x), h1 = __float2bfloat16(v.y);
    __nv_bfloat16 h2 = __float2bfloat16(v.z), h3 = __float2bfloat16(v.w);
    __nv_bfloat16 l0 = __float2bfloat16(v.x - __bfloat162float(h0));
    __nv_bfloat16 l1 = __float2bfloat16(v.y - __bfloat162float(h1));
    __nv_bfloat16 l2 = __float2bfloat16(v.z - __bfloat162float(h2));
    __nv_bfloat16 l3 = __float2bfloat16(v.w - __bfloat162float(h3));
    ((__nv_bfloat162*)g_inp_hi)[2 * i]     = __halves2bfloat162(h0, h1);
    ((__nv_bfloat162*)g_inp_hi)[2 * i + 1] = __halves2bfloat162(h2, h3);
    ((__nv_bfloat162*)g_inp_lo)[2 * i]     = __halves2bfloat162(l0, l1);
    ((__nv_bfloat162*)g_inp_lo)[2 * i + 1] = __halves2bfloat162(l2, l3);
    ((__half2*)g_inp_h)[2 * i]     = __floats2half2_rn(v.x, v.y);
    ((__half2*)g_inp_h)[2 * i + 1] = __floats2half2_rn(v.z, v.w);
}

// ---------------------------------------------------------------------------
// fused ctx prep (vectorized): 64s x 64d tile per block, one read of ctx ->
// bf16x2 hi/lo stores (row-major) + fp16x2 transpose stores
// ---------------------------------------------------------------------------
__global__ __launch_bounds__(256)
void fuse_ctx(const float* __restrict__ ctx)
{
    __shared__ float ts[64][65];
    const int b = blockIdx.z;
    const int d0 = blockIdx.x * 64;
    const int s0 = blockIdx.y * 64;
    const int tx = threadIdx.x, ty = threadIdx.y;   // 32 x 8
    #pragma unroll
    for (int r = ty; r < 64; r += 8) {
        const float2 v = *(const float2*)(ctx + (size_t)b * NSS * ND
                                          + (size_t)(s0 + r) * ND + d0 + 2 * tx);
        ts[r][2 * tx]     = v.x;
        ts[r][2 * tx + 1] = v.y;
        __nv_bfloat16 h0 = __float2bfloat16(v.x);
        __nv_bfloat16 h1 = __float2bfloat16(v.y);
        __nv_bfloat16 l0 = __float2bfloat16(v.x - __bfloat162float(h0));
        __nv_bfloat16 l1 = __float2bfloat16(v.y - __bfloat162float(h1));
        const size_t o = ((size_t)b * NSS + s0 + r) * ND + d0 + 2 * tx;
        *(__nv_bfloat162*)(g_ctx_hi + o) = __halves2bfloat162(h0, h1);
        *(__nv_bfloat162*)(g_ctx_lo + o) = __halves2bfloat162(l0, l1);
    }
    __syncthreads();
    #pragma unroll
    for (int r = ty; r < 64; r += 8) {
        float v0 = ts[2 * tx][r];
        float v1 = ts[2 * tx + 1][r];
        const size_t o = (size_t)b * ND * NSS + (size_t)(d0 + r) * NSS + s0 + 2 * tx;
        *(__half2*)(g_ctxT_h + o) = __floats2half2_rn(v0, v1);
    }
}

// ---------------------------------------------------------------------------
// W prep: W -> fp16, bias2[n] = bs * sum_{k<768} W[n,k] + b_out[n]
// ---------------------------------------------------------------------------
__global__ __launch_bounds__(256)
void wprep(const float* __restrict__ W, const float* __restrict__ bo,
           const float* __restrict__ bsp)
{
    const int n = blockIdx.x;
    const int tid = threadIdx.x;
    float sum = 0.f;
    #pragma unroll
    for (int k0 = 0; k0 < NK3; k0 += 1024) {
        const int k = k0 + tid * 4;
        float4 v = *(const float4*)(W + (size_t)n * NK3 + k);
        ((__half2*)(g_w_h + (size_t)n * NK3 + k))[0] = __floats2half2_rn(v.x, v.y);
        ((__half2*)(g_w_h + (size_t)n * NK3 + k))[1] = __floats2half2_rn(v.z, v.w);
        if (k < ND) sum += (v.x + v.y) + (v.z + v.w);
    }
    __shared__ float red[8];
    #pragma unroll
    for (int o = 16; o; o >>= 1) sum += __shfl_xor_sync(0xffffffffu, sum, o);
    if ((tid & 31) == 0) red[tid >> 5] = sum;
    __syncthreads();
    if (tid == 0) {
        float t = ((red[0] + red[1]) + (red[2] + red[3])) +
                  ((red[4] + red[5]) + (red[6] + red[7]));
        g_bias2[n] = __ldg(bsp) * t + __ldg(bo + n);
    }
}

// ---------------------------------------------------------------------------
// row softmax over S: reads fp32 logits, writes fp16 av (fast exp)
// ---------------------------------------------------------------------------
__global__ __launch_bounds__(256)
void softmax_k()
{
    const float* row = g_scores + (size_t)blockIdx.x * NSS;
    const int tid = threadIdx.x;
    const unsigned FULL = 0xffffffffu;
    float4 x = *(const float4*)(row + tid * 4);
    float m = fmaxf(fmaxf(x.x, x.y), fmaxf(x.z, x.w));
    __shared__ float sred[8];
    __shared__ float sred2[8];
    #pragma unroll
    for (int o = 16; o; o >>= 1) m = fmaxf(m, __shfl_xor_sync(FULL, m, o));
    if ((tid & 31) == 0) sred[tid >> 5] = m;
    __syncthreads();
    m = fmaxf(fmaxf(fmaxf(sred[0], sred[1]), fmaxf(sred[2], sred[3])),
              fmaxf(fmaxf(sred[4], sred[5]), fmaxf(sred[6], sred[7])));
    float e0 = __expf(x.x - m), e1 = __expf(x.y - m);
    float e2 = __expf(x.z - m), e3 = __expf(x.w - m);
    float s = (e0 + e1) + (e2 + e3);
    #pragma unroll
    for (int o = 16; o; o >>= 1) s += __shfl_xor_sync(FULL, s, o);
    if ((tid & 31) == 0) sred2[tid >> 5] = s;
    __syncthreads();
    s = ((sred2[0] + sred2[1]) + (sred2[2] + sred2[3])) +
        ((sred2[4] + sred2[5]) + (sred2[6] + sred2[7]));
    const float inv = 1.0f / s;
    __half* dst = g_av_h + (size_t)blockIdx.x * NSS + tid * 4;
    *(__half2*)(dst)     = __floats2half2_rn(e0 * inv, e1 * inv);
    *(__half2*)(dst + 2) = __floats2half2_rn(e2 * inv, e3 * inv);
}

// ---------------------------------------------------------------------------
// gate, phase 1: partial column sums over 128-row chunks (fp16 input)
// ---------------------------------------------------------------------------
__global__ __launch_bounds__(256)
void gate_part()
{
    const int s2 = blockIdx.x * 512 + threadIdx.x * 2;
    const int tc = blockIdx.y;
    const int b = blockIdx.z;
    const __half* p = g_av_h + (size_t)b * NTT * NSS + (size_t)tc * 128 * NSS + s2;
    float2 a0 = {0.f, 0.f}, a1 = {0.f, 0.f}, a2 = {0.f, 0.f}, a3 = {0.f, 0.f};
    #pragma unroll
    for (int t = 0; t < 128; t += 4) {
        float2 f0 = __half22float2(*(const __half2*)(p + (size_t)(t + 0) * NSS));
        float2 f1 = __half22float2(*(const __half2*)(p + (size_t)(t + 1) * NSS));
        float2 f2 = __half22float2(*(const __half2*)(p + (size_t)(t + 2) * NSS));
        float2 f3 = __half22float2(*(const __half2*)(p + (size_t)(t + 3) * NSS));
        a0.x += f0.x; a0.y += f0.y;
        a1.x += f1.x; a1.y += f1.y;
        a2.x += f2.x; a2.y += f2.y;
        a3.x += f3.x; a3.y += f3.y;
    }
    float2 r;
    r.x = (a0.x + a1.x) + (a2.x + a3.x);
    r.y = (a0.y + a1.y) + (a2.y + a3.y);
    *(float2*)(&g_gpart[tc][b * NSS + s2]) = r;
}

// gate, phase 2: reduce 8 partials + sigmoid
__global__ __launch_bounds__(256)
void gate_fin()
{
    const int gid = blockIdx.x * 256 + threadIdx.x;
    float s = 0.f;
    #pragma unroll
    for (int i = 0; i < 8; ++i) s += g_gpart[i][gid];
    g_gate[gid] = 1.0f / (1.0f + __expf(-s));
}

// ---------------------------------------------------------------------------
// av_g: reads fp16 av; out2 [T,B,S] = av*gate/1024 (fp32);
//       g_avg_h [B,T,S] = fp16(av*gate)
// ---------------------------------------------------------------------------
__global__ __launch_bounds__(256)
void avg_k(float* __restrict__ out2)
{
    const int bt = blockIdx.x;
    const int b = bt >> 10, t = bt & 1023;
    const int s = threadIdx.x * 4;
    const __half* src = g_av_h + (size_t)bt * NSS + s;
    float2 f01 = __half22float2(*(const __half2*)(src));
    float2 f23 = __half22float2(*(const __half2*)(src + 2));
    float4 g = *(const float4*)(g_gate + b * NSS + s);
    float4 v;
    v.x = f01.x * g.x; v.y = f01.y * g.y; v.z = f23.x * g.z; v.w = f23.y * g.w;
    const float pool = 1.0f / 1024.0f;
    *(float4*)(out2 + ((size_t)t * NB + b) * NSS + s) =
        make_float4(v.x * pool, v.y * pool, v.z * pool, v.w * pool);
    __half2* ph = (__half2*)(g_avg_h + (size_t)bt * NSS + s);
    ph[0] = __floats2half2_rn(v.x, v.y);
    ph[1] = __floats2half2_rn(v.z, v.w);
}

// ---------------------------------------------------------------------------
extern "C" void kernel_launch(void* const* d_in, const int* in_sizes, int n_in,
                              void* d_out, int out_size)
{
    const float* inp = (const float*)d_in[0];   // [B,T,768]
    const float* ctx = (const float*)d_in[1];   // [B,S,768]
    const float* W   = (const float*)d_in[2];   // [768,1536]
    const float* bo  = (const float*)d_in[3];   // [768]
    const float* ws  = (const float*)d_in[4];   // [1]
    const float* bs  = (const float*)d_in[5];   // [1]
    const float* pa  = (const float*)d_in[6];   // [1]
    float* out1 = (float*)d_out;                          // attn_h^T [T,B,768]
    float* out2 = out1 + (size_t)NTT * NB * ND;           // av_g^T   [T,B,S]

    cudaFuncSetAttribute(g1_gemm, cudaFuncAttributeMaxDynamicSharedMemorySize, SMEM_G1);
    cudaFuncSetAttribute(gemm_1t<0>, cudaFuncAttributeMaxDynamicSharedMemorySize, SMEM_1T);
    cudaFuncSetAttribute(gemm_1t<1>, cudaFuncAttributeMaxDynamicSharedMemorySize, SMEM_1T);

    fuse_inp<<<NB * NTT * ND / 4 / 256, 256>>>(inp);
    fuse_ctx<<<dim3(ND / 64, NSS / 64, NB), dim3(32, 8)>>>(ctx);
    wprep<<<ND, 256>>>(W, bo, bs);

    g1_gemm<<<dim3(8, 8, NB), 256, SMEM_G1>>>();
    softmax_k<<<NB * NTT, 256>>>();
    gate_part<<<dim3(2, 8, NB), 256>>>();
    gate_fin<<<NB * NSS / 256, 256>>>();
    avg_k<<<NB * NTT, 256>>>(out2);
    gemm_1t<0><<<dim3(6, 8, NB), 256, SMEM_1T>>>(ws, pa, out1);
    gemm_1t<1><<<dim3(6, 128, 1), 256, SMEM_1T>>>(ws, pa, out1);
}

// round 15
// speedup vs baseline: 1.1251x; 1.0058x over previous
#include <cuda_runtime.h>
#include <cuda_bf16.h>
#include <cuda_fp16.h>
#include <stdint.h>
#include <math.h>

#define NB 16
#define NTT 1024
#define NSS 1024
#define ND 768
#define NK3 1536

// ---------------------------------------------------------------------------
// scratch (static device globals — no allocations allowed)
// ---------------------------------------------------------------------------
__device__ float g_scores[(size_t)NB * NTT * NSS];         // G1 logits (fp32)
__device__ __half g_av_h[(size_t)NB * NTT * NSS];          // softmax result (fp16)
__device__ float g_gate[NB * NSS];
__device__ float g_gpart[8][NB * NSS];
__device__ float g_bias2[ND];
__device__ __nv_bfloat16 g_inp_hi[(size_t)NB * NTT * ND];  // GEMM1 A (3-term)
__device__ __nv_bfloat16 g_inp_lo[(size_t)NB * NTT * ND];
__device__ __nv_bfloat16 g_ctx_hi[(size_t)NB * NSS * ND];  // GEMM1 B (3-term)
__device__ __nv_bfloat16 g_ctx_lo[(size_t)NB * NSS * ND];
__device__ __half g_inp_h[(size_t)NB * NTT * ND];          // GEMM3 A part2
__device__ __half g_ctxT_h[(size_t)NB * ND * NSS];         // GEMM2 B
__device__ __half g_avg_h[(size_t)NB * NTT * NSS];         // GEMM2 A (av*gate)
__device__ __half g_cc_h[(size_t)NB * NTT * ND];           // GEMM3 A part1 (c*ws/1024)
__device__ __half g_w_h[ND * NK3];                         // GEMM3 B

// ---------------------------------------------------------------------------
// sm_80-compatible PTX helpers (NO tcgen05 — harness targets compute_103)
// ---------------------------------------------------------------------------
__device__ __forceinline__ uint32_t smem_to_u32(const void* p) {
    uint32_t a;
    asm("{ .reg .u64 t; cvta.to.shared.u64 t, %1; cvt.u32.u64 %0, t; }" : "=r"(a) : "l"(p));
    return a;
}

__device__ __forceinline__ void cpa16(uint32_t dst, const void* src) {
    asm volatile("cp.async.cg.shared.global [%0], [%1], 16;" :: "r"(dst), "l"(src));
}
#define CP_COMMIT() asm volatile("cp.async.commit_group;" ::: "memory")
#define CP_WAIT(n)  asm volatile("cp.async.wait_group %0;" :: "n"(n) : "memory")

__device__ __forceinline__ void ldsm4(uint32_t (&r)[4], uint32_t addr) {
    asm volatile("ldmatrix.sync.aligned.m8n8.x4.shared.b16 {%0,%1,%2,%3}, [%4];"
                 : "=r"(r[0]), "=r"(r[1]), "=r"(r[2]), "=r"(r[3]) : "r"(addr));
}

__device__ __forceinline__ void hmma_bf(float (&d)[4], const uint32_t (&a)[4],
                                        uint32_t b0, uint32_t b1) {
    asm volatile(
        "mma.sync.aligned.m16n8k16.row.col.f32.bf16.bf16.f32 "
        "{%0,%1,%2,%3}, {%4,%5,%6,%7}, {%8,%9}, {%0,%1,%2,%3};"
        : "+f"(d[0]), "+f"(d[1]), "+f"(d[2]), "+f"(d[3])
        : "r"(a[0]), "r"(a[1]), "r"(a[2]), "r"(a[3]), "r"(b0), "r"(b1));
}

__device__ __forceinline__ void hmma_f16(float (&d)[4], const uint32_t (&a)[4],
                                         uint32_t b0, uint32_t b1) {
    asm volatile(
        "mma.sync.aligned.m16n8k16.row.col.f32.f16.f16.f32 "
        "{%0,%1,%2,%3}, {%4,%5,%6,%7}, {%8,%9}, {%0,%1,%2,%3};"
        : "+f"(d[0]), "+f"(d[1]), "+f"(d[2]), "+f"(d[3])
        : "r"(a[0]), "r"(a[1]), "r"(a[2]), "r"(a[3]), "r"(b0), "r"(b1));
}

// fp16-accumulate variant (rate experiment — GEMM2 only)
__device__ __forceinline__ void hmma_h16(uint32_t (&d)[2], const uint32_t (&a)[4],
                                         uint32_t b0, uint32_t b1) {
    asm volatile(
        "mma.sync.aligned.m16n8k16.row.col.f16.f16.f16.f16 "
        "{%0,%1}, {%2,%3,%4,%5}, {%6,%7}, {%0,%1};"
        : "+r"(d[0]), "+r"(d[1])
        : "r"(a[0]), "r"(a[1]), "r"(a[2]), "r"(a[3]), "r"(b0), "r"(b1));
}

// byte offset of 16-bit elem (r, c) inside a 128x32 SW64-swizzled tile (64B rows)
__device__ __forceinline__ uint32_t swz(int r, int c) {
    int off = (r << 6) + (c << 1);
    return (uint32_t)(off ^ ((off >> 3) & 0x30));
}

// ===========================================================================
// GEMM1: bf16 3-term split (AhBh + AhBl + AlBh), 128x128 tile, K-chunk 32
// 3-stage pipeline (wait -> sync -> prefetch -> compute), 2 CTAs/SM.  [R10]
// ===========================================================================
static constexpr int TILE_B   = 8192;        // one 128x32 16-bit tile (SW64)
static constexpr int STAGE_B  = 4 * TILE_B;  // Ah, Al, Bh, Bl = 32 KB
static constexpr int SMEM_G1  = 3 * STAGE_B; // 96 KB -> 2 CTAs/SM

__device__ __forceinline__ void load_stage_g1(
    const __nv_bfloat16* __restrict__ ah, const __nv_bfloat16* __restrict__ al,
    const __nv_bfloat16* __restrict__ bh, const __nv_bfloat16* __restrict__ bl,
    int m0, int n0, int k0, uint32_t sbase)
{
    const int tid = threadIdx.x;
    #pragma unroll
    for (int j = 0; j < 2; ++j) {
        const int id = tid + 256 * j;
        const int r  = id >> 2;
        const int c  = (id & 3) << 3;
        const uint32_t off = swz(r, c);
        cpa16(sbase + off,              ah + (size_t)(m0 + r) * ND + k0 + c);
        cpa16(sbase + TILE_B + off,     al + (size_t)(m0 + r) * ND + k0 + c);
        cpa16(sbase + 2 * TILE_B + off, bh + (size_t)(n0 + r) * ND + k0 + c);
        cpa16(sbase + 3 * TILE_B + off, bl + (size_t)(n0 + r) * ND + k0 + c);
    }
}

__global__ __launch_bounds__(256, 2)
void g1_gemm()
{
    extern __shared__ char smem[];
    const uint32_t sb = smem_to_u32(smem);
    const int tid = threadIdx.x;
    const int lane = tid & 31, wid = tid >> 5;
    const int rm = (wid & 3) * 32;
    const int cn = (wid >> 2) * 64;

    const int m0 = blockIdx.y * 128;
    const int n0 = blockIdx.x * 128;
    const int bz = blockIdx.z;

    const __nv_bfloat16* Ah = g_inp_hi + (size_t)bz * NTT * ND;
    const __nv_bfloat16* Al = g_inp_lo + (size_t)bz * NTT * ND;
    const __nv_bfloat16* Bh = g_ctx_hi + (size_t)bz * NSS * ND;
    const __nv_bfloat16* Bl = g_ctx_lo + (size_t)bz * NSS * ND;
    const int NC = ND / 32;

    float acc[2][8][4];
    #pragma unroll
    for (int i = 0; i < 2; ++i)
        #pragma unroll
        for (int j = 0; j < 8; ++j)
            #pragma unroll
            for (int v = 0; v < 4; ++v) acc[i][j][v] = 0.f;

    const int q = lane >> 3, l7 = lane & 7;
    const int ar = rm + ((q & 1) << 3) + l7;
    const int acq = (q >> 1) << 3;
    const int brq = ((q >> 1) << 3) + l7;
    const int bcq = (q & 1) << 3;

    load_stage_g1(Ah, Al, Bh, Bl, m0, n0, 0, sb);
    CP_COMMIT();
    load_stage_g1(Ah, Al, Bh, Bl, m0, n0, 32, sb + STAGE_B);
    CP_COMMIT();

    int buf = 0;
    for (int kc = 0; kc < NC; ++kc) {
        if (kc + 1 < NC) { CP_WAIT(1); } else { CP_WAIT(0); }
        __syncthreads();
        if (kc + 2 < NC) {
            int nbuf = buf + 2; if (nbuf >= 3) nbuf -= 3;
            load_stage_g1(Ah, Al, Bh, Bl, m0, n0, (kc + 2) * 32,
                          sb + (uint32_t)nbuf * STAGE_B);
            CP_COMMIT();
        }
        const uint32_t sbase = sb + (uint32_t)buf * STAGE_B;
        #pragma unroll
        for (int k16 = 0; k16 < 2; ++k16) {
            const int kk = k16 * 16;
            uint32_t A0[4], A1[4], L0[4], L1[4];
            ldsm4(A0, sbase + swz(ar, kk + acq));
            ldsm4(A1, sbase + swz(ar + 16, kk + acq));
            ldsm4(L0, sbase + TILE_B + swz(ar, kk + acq));
            ldsm4(L1, sbase + TILE_B + swz(ar + 16, kk + acq));
            #pragma unroll
            for (int np = 0; np < 4; ++np) {
                uint32_t Bh4[4], Bl4[4];
                const uint32_t boff = swz(cn + np * 16 + brq, kk + bcq);
                ldsm4(Bh4, sbase + 2 * TILE_B + boff);
                ldsm4(Bl4, sbase + 3 * TILE_B + boff);
                hmma_bf(acc[0][2 * np],     A0, Bh4[0], Bh4[1]);
                hmma_bf(acc[0][2 * np + 1], A0, Bh4[2], Bh4[3]);
                hmma_bf(acc[1][2 * np],     A1, Bh4[0], Bh4[1]);
                hmma_bf(acc[1][2 * np + 1], A1, Bh4[2], Bh4[3]);
                hmma_bf(acc[0][2 * np],     A0, Bl4[0], Bl4[1]);
                hmma_bf(acc[0][2 * np + 1], A0, Bl4[2], Bl4[3]);
                hmma_bf(acc[1][2 * np],     A1, Bl4[0], Bl4[1]);
                hmma_bf(acc[1][2 * np + 1], A1, Bl4[2], Bl4[3]);
                hmma_bf(acc[0][2 * np],     L0, Bh4[0], Bh4[1]);
                hmma_bf(acc[0][2 * np + 1], L0, Bh4[2], Bh4[3]);
                hmma_bf(acc[1][2 * np],     L1, Bh4[0], Bh4[1]);
                hmma_bf(acc[1][2 * np + 1], L1, Bh4[2], Bh4[3]);
            }
        }
        if (++buf == 3) buf = 0;
    }

    const int rbase = m0 + rm + (lane >> 2);
    const int cbase = n0 + cn + ((lane & 3) << 1);
    float* dst = g_scores + ((size_t)bz << 20);
    #pragma unroll
    for (int mt = 0; mt < 2; ++mt)
        #pragma unroll
        for (int h = 0; h < 2; ++h) {
            const int row = rbase + mt * 16 + h * 8;
            #pragma unroll
            for (int nt = 0; nt < 8; ++nt)
                *(float2*)(dst + (size_t)row * NSS + cbase + nt * 8) =
                    make_float2(acc[mt][nt][2 * h], acc[mt][nt][2 * h + 1]);
        }
}

// ===========================================================================
// shared loader for 1-term fp16 GEMMs (128x128 tile, K-chunk 32, 4-stage)
// ===========================================================================
static constexpr int STG1T   = 2 * TILE_B;      // A + B = 16 KB
static constexpr int SMEM_1T = 4 * STG1T;       // 64 KB -> 2 CTAs/SM

__device__ __forceinline__ void load_stage_1t(
    const __half* __restrict__ a, const __half* __restrict__ b,
    int lda, int ldb, int m0, int n0, int ka, int kb, uint32_t sbase)
{
    const int tid = threadIdx.x;
    #pragma unroll
    for (int j = 0; j < 2; ++j) {
        const int id = tid + 256 * j;
        const int r  = id >> 2;
        const int c  = (id & 3) << 3;
        const uint32_t off = swz(r, c);
        cpa16(sbase + off,          a + (size_t)(m0 + r) * lda + ka + c);
        cpa16(sbase + TILE_B + off, b + (size_t)(n0 + r) * ldb + kb + c);
    }
}

// ===========================================================================
// GEMM2 (fp16 accumulate): c' = avg @ ctxT^T (K=1024)
//   -> cc_h = fp16(c' * ws / 1024)
// ===========================================================================
__global__ __launch_bounds__(256, 2)
void g2_gemm(const float* __restrict__ wsp)
{
    extern __shared__ char smem[];
    const uint32_t sb = smem_to_u32(smem);
    const int tid = threadIdx.x;
    const int lane = tid & 31, wid = tid >> 5;
    const int rm = (wid & 3) * 32;
    const int cn = (wid >> 2) * 64;

    const int m0 = blockIdx.y * 128;
    const int n0 = blockIdx.x * 128;
    const int bz = blockIdx.z;

    const __half* A = g_avg_h + (size_t)bz * NTT * NSS;
    const __half* B = g_ctxT_h + (size_t)bz * ND * NSS;
    const int NC = NSS / 32;

    uint32_t acc[2][8][2];
    #pragma unroll
    for (int i = 0; i < 2; ++i)
        #pragma unroll
        for (int j = 0; j < 8; ++j) { acc[i][j][0] = 0u; acc[i][j][1] = 0u; }

    const int q = lane >> 3, l7 = lane & 7;
    const int ar = rm + ((q & 1) << 3) + l7;
    const int acq = (q >> 1) << 3;
    const int brq = ((q >> 1) << 3) + l7;
    const int bcq = (q & 1) << 3;

    load_stage_1t(A, B, NSS, NSS, m0, n0, 0, 0, sb);
    CP_COMMIT();
    load_stage_1t(A, B, NSS, NSS, m0, n0, 32, 32, sb + STG1T);
    CP_COMMIT();

    for (int kc = 0; kc < NC; ++kc) {
        if (kc + 2 < NC) {
            load_stage_1t(A, B, NSS, NSS, m0, n0, (kc + 2) * 32, (kc + 2) * 32,
                          sb + (uint32_t)((kc + 2) & 3) * STG1T);
            CP_COMMIT();
            CP_WAIT(2);
        } else if (kc + 1 < NC) {
            CP_WAIT(1);
        } else {
            CP_WAIT(0);
        }
        __syncthreads();

        const uint32_t sbase = sb + (uint32_t)(kc & 3) * STG1T;
        #pragma unroll
        for (int k16 = 0; k16 < 2; ++k16) {
            const int kk = k16 * 16;
            uint32_t A0[4], A1[4];
            ldsm4(A0, sbase + swz(ar, kk + acq));
            ldsm4(A1, sbase + swz(ar + 16, kk + acq));
            #pragma unroll
            for (int np = 0; np < 4; ++np) {
                uint32_t B4[4];
                ldsm4(B4, sbase + TILE_B + swz(cn + np * 16 + brq, kk + bcq));
                hmma_h16(acc[0][2 * np],     A0, B4[0], B4[1]);
                hmma_h16(acc[0][2 * np + 1], A0, B4[2], B4[3]);
                hmma_h16(acc[1][2 * np],     A1, B4[0], B4[1]);
                hmma_h16(acc[1][2 * np + 1], A1, B4[2], B4[3]);
            }
        }
    }

    // epilogue: acc u32 = 2 halves at cols {cbase, cbase+1}; d[h] row = base + 8h
    const int rbase = m0 + rm + (lane >> 2);
    const int cbase = n0 + cn + ((lane & 3) << 1);
    const float sc = __ldg(wsp) * (1.0f / 1024.0f);
    #pragma unroll
    for (int mt = 0; mt < 2; ++mt)
        #pragma unroll
        for (int h = 0; h < 2; ++h) {
            const int row = rbase + mt * 16 + h * 8;
            __half* dst = g_cc_h + ((size_t)bz * NTT + row) * ND;
            #pragma unroll
            for (int nt = 0; nt < 8; ++nt) {
                const float2 f = __half22float2(*(__half2*)&acc[mt][nt][h]);
                *(__half2*)(dst + cbase + nt * 8) =
                    __floats2half2_rn(f.x * sc, f.y * sc);
            }
        }
}

// ===========================================================================
// GEMM3 (fp32 accumulate): h = [cc;inp_h] @ w_h^T + bias2, PReLU -> out1
// ===========================================================================
__global__ __launch_bounds__(256, 2)
void g3_gemm(const float* __restrict__ pap, float* __restrict__ out1)
{
    extern __shared__ char smem[];
    const uint32_t sb = smem_to_u32(smem);
    const int tid = threadIdx.x;
    const int lane = tid & 31, wid = tid >> 5;
    const int rm = (wid & 3) * 32;
    const int cn = (wid >> 2) * 64;

    const int m0 = blockIdx.y * 128;
    const int n0 = blockIdx.x * 128;

    const __half* A = g_cc_h;
    const __half* B = g_w_h;
    const int NC = NK3 / 32;

    float acc[2][8][4];
    #pragma unroll
    for (int i = 0; i < 2; ++i)
        #pragma unroll
        for (int j = 0; j < 8; ++j)
            #pragma unroll
            for (int v = 0; v < 4; ++v) acc[i][j][v] = 0.f;

    const int q = lane >> 3, l7 = lane & 7;
    const int ar = rm + ((q & 1) << 3) + l7;
    const int acq = (q >> 1) << 3;
    const int brq = ((q >> 1) << 3) + l7;
    const int bcq = (q & 1) << 3;

    load_stage_1t(A, B, ND, NK3, m0, n0, 0, 0, sb);
    CP_COMMIT();
    load_stage_1t(A, B, ND, NK3, m0, n0, 32, 32, sb + STG1T);
    CP_COMMIT();

    for (int kc = 0; kc < NC; ++kc) {
        if (kc + 2 < NC) {
            const __half* a = A;
            int ka = (kc + 2) * 32;
            const int kb = ka;
            if (ka >= ND) { a = g_inp_h; ka -= ND; }
            load_stage_1t(a, B, ND, NK3, m0, n0, ka, kb,
                          sb + (uint32_t)((kc + 2) & 3) * STG1T);
            CP_COMMIT();
            CP_WAIT(2);
        } else if (kc + 1 < NC) {
            CP_WAIT(1);
        } else {
            CP_WAIT(0);
        }
        __syncthreads();

        const uint32_t sbase = sb + (uint32_t)(kc & 3) * STG1T;
        #pragma unroll
        for (int k16 = 0; k16 < 2; ++k16) {
            const int kk = k16 * 16;
            uint32_t A0[4], A1[4];
            ldsm4(A0, sbase + swz(ar, kk + acq));
            ldsm4(A1, sbase + swz(ar + 16, kk + acq));
            #pragma unroll
            for (int np = 0; np < 4; ++np) {
                uint32_t B4[4];
                ldsm4(B4, sbase + TILE_B + swz(cn + np * 16 + brq, kk + bcq));
                hmma_f16(acc[0][2 * np],     A0, B4[0], B4[1]);
                hmma_f16(acc[0][2 * np + 1], A0, B4[2], B4[3]);
                hmma_f16(acc[1][2 * np],     A1, B4[0], B4[1]);
                hmma_f16(acc[1][2 * np + 1], A1, B4[2], B4[3]);
            }
        }
    }

    const int rbase = m0 + rm + (lane >> 2);
    const int cbase = n0 + cn + ((lane & 3) << 1);
    const float pa = __ldg(pap);
    #pragma unroll
    for (int mt = 0; mt < 2; ++mt)
        #pragma unroll
        for (int h = 0; h < 2; ++h) {
            const int row = rbase + mt * 16 + h * 8;
            const int bb = row >> 10, tt = row & 1023;
            float* dst = out1 + ((size_t)tt * NB + bb) * ND;
            #pragma unroll
            for (int nt = 0; nt < 8; ++nt) {
                const int col = cbase + nt * 8;
                float v0 = acc[mt][nt][2 * h]     + __ldg(&g_bias2[col]);
                float v1 = acc[mt][nt][2 * h + 1] + __ldg(&g_bias2[col + 1]);
                v0 = (v0 >= 0.f) ? v0 : pa * v0;
                v1 = (v1 >= 0.f) ? v1 : pa * v1;
                *(float2*)(dst + col) = make_float2(v0, v1);
            }
        }
}

// ---------------------------------------------------------------------------
// fused inp prep + W prep (merged grids):
//   blocks [0, NIB):      inp fp32 -> bf16 hi/lo + fp16 (one read)
//   blocks [NIB, NIB+ND): W -> fp16 + bias2[n]
// ---------------------------------------------------------------------------
static constexpr int NIB = NB * NTT * ND / 4 / 256;   // 12288

__global__ __launch_bounds__(256)
void fuse_inp(const float* __restrict__ src, const float* __restrict__ W,
              const float* __restrict__ bo, const float* __restrict__ bsp)
{
    __shared__ float red[8];
    if (blockIdx.x >= NIB) {
        const int n = blockIdx.x - NIB;
        const int tid = threadIdx.x;
        float sum = 0.f;
        #pragma unroll
        for (int k0 = 0; k0 < NK3; k0 += 1024) {
            const int k = k0 + tid * 4;
            float4 v = *(const float4*)(W + (size_t)n * NK3 + k);
            ((__half2*)(g_w_h + (size_t)n * NK3 + k))[0] = __floats2half2_rn(v.x, v.y);
            ((__half2*)(g_w_h + (size_t)n * NK3 + k))[1] = __floats2half2_rn(v.z, v.w);
            if (k < ND) sum += (v.x + v.y) + (v.z + v.w);
        }
        #pragma unroll
        for (int o = 16; o; o >>= 1) sum += __shfl_xor_sync(0xffffffffu, sum, o);
        if ((tid & 31) == 0) red[tid >> 5] = sum;
        __syncthreads();
        if (tid == 0) {
            float t = ((red[0] + red[1]) + (red[2] + red[3])) +
                      ((red[4] + red[5]) + (red[6] + red[7]));
            g_bias2[n] = __ldg(bsp) * t + __ldg(bo + n);
        }
        return;
    }
    const size_t i = (size_t)blockIdx.x * 256 + threadIdx.x;
    float4 v = ((const float4*)src)[i];
    __nv_bfloat16 h0 = __float2bfloat16(v.x), h1 = __float2bfloat16(v.y);
    __nv_bfloat16 h2 = __float2bfloat16(v.z), h3 = __float2bfloat16(v.w);
    __nv_bfloat16 l0 = __float2bfloat16(v.x - __bfloat162float(h0));
    __nv_bfloat16 l1 = __float2bfloat16(v.y - __bfloat162float(h1));
    __nv_bfloat16 l2 = __float2bfloat16(v.z - __bfloat162float(h2));
    __nv_bfloat16 l3 = __float2bfloat16(v.w - __bfloat162float(h3));
    ((__nv_bfloat162*)g_inp_hi)[2 * i]     = __halves2bfloat162(h0, h1);
    ((__nv_bfloat162*)g_inp_hi)[2 * i + 1] = __halves2bfloat162(h2, h3);
    ((__nv_bfloat162*)g_inp_lo)[2 * i]     = __halves2bfloat162(l0, l1);
    ((__nv_bfloat162*)g_inp_lo)[2 * i + 1] = __halves2bfloat162(l2, l3);
    ((__half2*)g_inp_h)[2 * i]     = __floats2half2_rn(v.x, v.y);
    ((__half2*)g_inp_h)[2 * i + 1] = __floats2half2_rn(v.z, v.w);
}

// ---------------------------------------------------------------------------
// fused ctx prep (vectorized): 64s x 64d tile per block
// ---------------------------------------------------------------------------
__global__ __launch_bounds__(256)
void fuse_ctx(const float* __restrict__ ctx)
{
    __shared__ float ts[64][65];
    const int b = blockIdx.z;
    const int d0 = blockIdx.x * 64;
    const int s0 = blockIdx.y * 64;
    const int tx = threadIdx.x, ty = threadIdx.y;   // 32 x 8
    #pragma unroll
    for (int r = ty; r < 64; r += 8) {
        const float2 v = *(const float2*)(ctx + (size_t)b * NSS * ND
                                          + (size_t)(s0 + r) * ND + d0 + 2 * tx);
        ts[r][2 * tx]     = v.x;
        ts[r][2 * tx + 1] = v.y;
        __nv_bfloat16 h0 = __float2bfloat16(v.x);
        __nv_bfloat16 h1 = __float2bfloat16(v.y);
        __nv_bfloat16 l0 = __float2bfloat16(v.x - __bfloat162float(h0));
        __nv_bfloat16 l1 = __float2bfloat16(v.y - __bfloat162float(h1));
        const size_t o = ((size_t)b * NSS + s0 + r) * ND + d0 + 2 * tx;
        *(__nv_bfloat162*)(g_ctx_hi + o) = __halves2bfloat162(h0, h1);
        *(__nv_bfloat162*)(g_ctx_lo + o) = __halves2bfloat162(l0, l1);
    }
    __syncthreads();
    #pragma unroll
    for (int r = ty; r < 64; r += 8) {
        float v0 = ts[2 * tx][r];
        float v1 = ts[2 * tx + 1][r];
        const size_t o = (size_t)b * ND * NSS + (size_t)(d0 + r) * NSS + s0 + 2 * tx;
        *(__half2*)(g_ctxT_h + o) = __floats2half2_rn(v0, v1);
    }
}

// ---------------------------------------------------------------------------
// row softmax over S: reads fp32 logits, writes fp16 av (fast exp)
// ---------------------------------------------------------------------------
__global__ __launch_bounds__(256)
void softmax_k()
{
    const float* row = g_scores + (size_t)blockIdx.x * NSS;
    const int tid = threadIdx.x;
    const unsigned FULL = 0xffffffffu;
    float4 x = *(const float4*)(row + tid * 4);
    float m = fmaxf(fmaxf(x.x, x.y), fmaxf(x.z, x.w));
    __shared__ float sred[8];
    __shared__ float sred2[8];
    #pragma unroll
    for (int o = 16; o; o >>= 1) m = fmaxf(m, __shfl_xor_sync(FULL, m, o));
    if ((tid & 31) == 0) sred[tid >> 5] = m;
    __syncthreads();
    m = fmaxf(fmaxf(fmaxf(sred[0], sred[1]), fmaxf(sred[2], sred[3])),
              fmaxf(fmaxf(sred[4], sred[5]), fmaxf(sred[6], sred[7])));
    float e0 = __expf(x.x - m), e1 = __expf(x.y - m);
    float e2 = __expf(x.z - m), e3 = __expf(x.w - m);
    float s = (e0 + e1) + (e2 + e3);
    #pragma unroll
    for (int o = 16; o; o >>= 1) s += __shfl_xor_sync(FULL, s, o);
    if ((tid & 31) == 0) sred2[tid >> 5] = s;
    __syncthreads();
    s = ((sred2[0] + sred2[1]) + (sred2[2] + sred2[3])) +
        ((sred2[4] + sred2[5]) + (sred2[6] + sred2[7]));
    const float inv = 1.0f / s;
    __half* dst = g_av_h + (size_t)blockIdx.x * NSS + tid * 4;
    *(__half2*)(dst)     = __floats2half2_rn(e0 * inv, e1 * inv);
    *(__half2*)(dst + 2) = __floats2half2_rn(e2 * inv, e3 * inv);
}

// ---------------------------------------------------------------------------
// gate, phase 1: partial column sums over 128-row chunks (fp16 input)
// ---------------------------------------------------------------------------
__global__ __launch_bounds__(256)
void gate_part()
{
    const int s2 = blockIdx.x * 512 + threadIdx.x * 2;
    const int tc = blockIdx.y;
    const int b = blockIdx.z;
    const __half* p = g_av_h + (size_t)b * NTT * NSS + (size_t)tc * 128 * NSS + s2;
    float2 a0 = {0.f, 0.f}, a1 = {0.f, 0.f}, a2 = {0.f, 0.f}, a3 = {0.f, 0.f};
    #pragma unroll
    for (int t = 0; t < 128; t += 4) {
        float2 f0 = __half22float2(*(const __half2*)(p + (size_t)(t + 0) * NSS));
        float2 f1 = __half22float2(*(const __half2*)(p + (size_t)(t + 1) * NSS));
        float2 f2 = __half22float2(*(const __half2*)(p + (size_t)(t + 2) * NSS));
        float2 f3 = __half22float2(*(const __half2*)(p + (size_t)(t + 3) * NSS));
        a0.x += f0.x; a0.y += f0.y;
        a1.x += f1.x; a1.y += f1.y;
        a2.x += f2.x; a2.y += f2.y;
        a3.x += f3.x; a3.y += f3.y;
    }
    float2 r;
    r.x = (a0.x + a1.x) + (a2.x + a3.x);
    r.y = (a0.y + a1.y) + (a2.y + a3.y);
    *(float2*)(&g_gpart[tc][b * NSS + s2]) = r;
}

// gate, phase 2: reduce 8 partials + sigmoid
__global__ __launch_bounds__(256)
void gate_fin()
{
    const int gid = blockIdx.x * 256 + threadIdx.x;
    float s = 0.f;
    #pragma unroll
    for (int i = 0; i < 8; ++i) s += g_gpart[i][gid];
    g_gate[gid] = 1.0f / (1.0f + __expf(-s));
}

// ---------------------------------------------------------------------------
// av_g: reads fp16 av; out2 [T,B,S] = av*gate/1024 (fp32);
//       g_avg_h [B,T,S] = fp16(av*gate)
// ---------------------------------------------------------------------------
__global__ __launch_bounds__(256)
void avg_k(float* __restrict__ out2)
{
    const int bt = blockIdx.x;
    const int b = bt >> 10, t = bt & 1023;
    const int s = threadIdx.x * 4;
    const __half* src = g_av_h + (size_t)bt * NSS + s;
    float2 f01 = __half22float2(*(const __half2*)(src));
    float2 f23 = __half22float2(*(const __half2*)(src + 2));
    float4 g = *(const float4*)(g_gate + b * NSS + s);
    float4 v;
    v.x = f01.x * g.x; v.y = f01.y * g.y; v.z = f23.x * g.z; v.w = f23.y * g.w;
    const float pool = 1.0f / 1024.0f;
    *(float4*)(out2 + ((size_t)t * NB + b) * NSS + s) =
        make_float4(v.x * pool, v.y * pool, v.z * pool, v.w * pool);
    __half2* ph = (__half2*)(g_avg_h + (size_t)bt * NSS + s);
    ph[0] = __floats2half2_rn(v.x, v.y);
    ph[1] = __floats2half2_rn(v.z, v.w);
}

// ---------------------------------------------------------------------------
extern "C" void kernel_launch(void* const* d_in, const int* in_sizes, int n_in,
                              void* d_out, int out_size)
{
    const float* inp = (const float*)d_in[0];   // [B,T,768]
    const float* ctx = (const float*)d_in[1];   // [B,S,768]
    const float* W   = (const float*)d_in[2];   // [768,1536]
    const float* bo  = (const float*)d_in[3];   // [768]
    const float* ws  = (const float*)d_in[4];   // [1]
    const float* bs  = (const float*)d_in[5];   // [1]
    const float* pa  = (const float*)d_in[6];   // [1]
    float* out1 = (float*)d_out;                          // attn_h^T [T,B,768]
    float* out2 = out1 + (size_t)NTT * NB * ND;           // av_g^T   [T,B,S]

    cudaFuncSetAttribute(g1_gemm, cudaFuncAttributeMaxDynamicSharedMemorySize, SMEM_G1);
    cudaFuncSetAttribute(g2_gemm, cudaFuncAttributeMaxDynamicSharedMemorySize, SMEM_1T);
    cudaFuncSetAttribute(g3_gemm, cudaFuncAttributeMaxDynamicSharedMemorySize, SMEM_1T);

    fuse_inp<<<NIB + ND, 256>>>(inp, W, bo, bs);
    fuse_ctx<<<dim3(ND / 64, NSS / 64, NB), dim3(32, 8)>>>(ctx);

    g1_gemm<<<dim3(8, 8, NB), 256, SMEM_G1>>>();
    softmax_k<<<NB * NTT, 256>>>();
    gate_part<<<dim3(2, 8, NB), 256>>>();
    gate_fin<<<NB * NSS / 256, 256>>>();
    avg_k<<<NB * NTT, 256>>>(out2);
    g2_gemm<<<dim3(6, 8, NB), 256, SMEM_1T>>>(ws);
    g3_gemm<<<dim3(6, 128, 1), 256, SMEM_1T>>>(pa, out1);
}

// round 16
// speedup vs baseline: 1.1404x; 1.0136x over previous
#include <cuda_runtime.h>
#include <cuda_bf16.h>
#include <cuda_fp16.h>
#include <stdint.h>
#include <math.h>

#define NB 16
#define NTT 1024
#define NSS 1024
#define ND 768
#define NK3 1536

// ---------------------------------------------------------------------------
// scratch (static device globals — no allocations allowed)
// ---------------------------------------------------------------------------
__device__ float g_scores[(size_t)NB * NTT * NSS];         // G1 logits (fp32)
__device__ __half g_av_h[(size_t)NB * NTT * NSS];          // softmax result (fp16)
__device__ float g_gate[NB * NSS];
__device__ float g_gpart[8][NB * NSS];
__device__ float g_bias2[ND];
__device__ __nv_bfloat16 g_inp_hi[(size_t)NB * NTT * ND];  // GEMM1 A (3-term)
__device__ __nv_bfloat16 g_inp_lo[(size_t)NB * NTT * ND];
__device__ __nv_bfloat16 g_ctx_hi[(size_t)NB * NSS * ND];  // GEMM1 B (3-term)
__device__ __nv_bfloat16 g_ctx_lo[(size_t)NB * NSS * ND];
__device__ __half g_inp_h[(size_t)NB * NTT * ND];          // GEMM3 A part2
__device__ __half g_ctxT_h[(size_t)NB * ND * NSS];         // GEMM2 B
__device__ __half g_avg_h[(size_t)NB * NTT * NSS];         // GEMM2 A (av*gate)
__device__ __half g_cc_h[(size_t)NB * NTT * ND];           // GEMM3 A part1 (c*ws/1024)
__device__ __half g_w_h[ND * NK3];                         // GEMM3 B

// ---------------------------------------------------------------------------
// sm_80-compatible PTX helpers (NO tcgen05 — harness targets compute_103)
// ---------------------------------------------------------------------------
__device__ __forceinline__ uint32_t smem_to_u32(const void* p) {
    uint32_t a;
    asm("{ .reg .u64 t; cvta.to.shared.u64 t, %1; cvt.u32.u64 %0, t; }" : "=r"(a) : "l"(p));
    return a;
}

__device__ __forceinline__ void cpa16(uint32_t dst, const void* src) {
    asm volatile("cp.async.cg.shared.global [%0], [%1], 16;" :: "r"(dst), "l"(src));
}
#define CP_COMMIT() asm volatile("cp.async.commit_group;" ::: "memory")
#define CP_WAIT(n)  asm volatile("cp.async.wait_group %0;" :: "n"(n) : "memory")

__device__ __forceinline__ void ldsm4(uint32_t (&r)[4], uint32_t addr) {
    asm volatile("ldmatrix.sync.aligned.m8n8.x4.shared.b16 {%0,%1,%2,%3}, [%4];"
                 : "=r"(r[0]), "=r"(r[1]), "=r"(r[2]), "=r"(r[3]) : "r"(addr));
}

__device__ __forceinline__ void hmma_bf(float (&d)[4], const uint32_t (&a)[4],
                                        uint32_t b0, uint32_t b1) {
    asm volatile(
        "mma.sync.aligned.m16n8k16.row.col.f32.bf16.bf16.f32 "
        "{%0,%1,%2,%3}, {%4,%5,%6,%7}, {%8,%9}, {%0,%1,%2,%3};"
        : "+f"(d[0]), "+f"(d[1]), "+f"(d[2]), "+f"(d[3])
        : "r"(a[0]), "r"(a[1]), "r"(a[2]), "r"(a[3]), "r"(b0), "r"(b1));
}

__device__ __forceinline__ void hmma_f16(float (&d)[4], const uint32_t (&a)[4],
                                         uint32_t b0, uint32_t b1) {
    asm volatile(
        "mma.sync.aligned.m16n8k16.row.col.f32.f16.f16.f32 "
        "{%0,%1,%2,%3}, {%4,%5,%6,%7}, {%8,%9}, {%0,%1,%2,%3};"
        : "+f"(d[0]), "+f"(d[1]), "+f"(d[2]), "+f"(d[3])
        : "r"(a[0]), "r"(a[1]), "r"(a[2]), "r"(a[3]), "r"(b0), "r"(b1));
}

// fp16-accumulate variant (GEMM2)
__device__ __forceinline__ void hmma_h16(uint32_t (&d)[2], const uint32_t (&a)[4],
                                         uint32_t b0, uint32_t b1) {
    asm volatile(
        "mma.sync.aligned.m16n8k16.row.col.f16.f16.f16.f16 "
        "{%0,%1}, {%2,%3,%4,%5}, {%6,%7}, {%0,%1};"
        : "+r"(d[0]), "+r"(d[1])
        : "r"(a[0]), "r"(a[1]), "r"(a[2]), "r"(a[3]), "r"(b0), "r"(b1));
}

// byte offset of 16-bit elem (r, c) inside a 128x32 SW64-swizzled tile (64B rows)
__device__ __forceinline__ uint32_t swz(int r, int c) {
    int off = (r << 6) + (c << 1);
    return (uint32_t)(off ^ ((off >> 3) & 0x30));
}

// ===========================================================================
// GEMM1: bf16 3-term split (AhBh + AhBl + AlBh), 128x128 tile, K-chunk 32
// ===========================================================================
static constexpr int TILE_B   = 8192;        // one 128x32 16-bit tile (SW64)
static constexpr int STAGE_B  = 4 * TILE_B;  // Ah, Al, Bh, Bl = 32 KB
static constexpr int SMEM_G1  = 3 * STAGE_B; // 96 KB -> 2 CTAs/SM

__device__ __forceinline__ void load_stage_g1(
    const __nv_bfloat16* __restrict__ ah, const __nv_bfloat16* __restrict__ al,
    const __nv_bfloat16* __restrict__ bh, const __nv_bfloat16* __restrict__ bl,
    int m0, int n0, int k0, uint32_t sbase)
{
    const int tid = threadIdx.x;
    #pragma unroll
    for (int j = 0; j < 2; ++j) {
        const int id = tid + 256 * j;
        const int r  = id >> 2;
        const int c  = (id & 3) << 3;
        const uint32_t off = swz(r, c);
        cpa16(sbase + off,              ah + (size_t)(m0 + r) * ND + k0 + c);
        cpa16(sbase + TILE_B + off,     al + (size_t)(m0 + r) * ND + k0 + c);
        cpa16(sbase + 2 * TILE_B + off, bh + (size_t)(n0 + r) * ND + k0 + c);
        cpa16(sbase + 3 * TILE_B + off, bl + (size_t)(n0 + r) * ND + k0 + c);
    }
}

__global__ __launch_bounds__(256, 2)
void g1_gemm()
{
    cudaGridDependencySynchronize();
    extern __shared__ char smem[];
    const uint32_t sb = smem_to_u32(smem);
    const int tid = threadIdx.x;
    const int lane = tid & 31, wid = tid >> 5;
    const int rm = (wid & 3) * 32;
    const int cn = (wid >> 2) * 64;

    const int m0 = blockIdx.y * 128;
    const int n0 = blockIdx.x * 128;
    const int bz = blockIdx.z;

    const __nv_bfloat16* Ah = g_inp_hi + (size_t)bz * NTT * ND;
    const __nv_bfloat16* Al = g_inp_lo + (size_t)bz * NTT * ND;
    const __nv_bfloat16* Bh = g_ctx_hi + (size_t)bz * NSS * ND;
    const __nv_bfloat16* Bl = g_ctx_lo + (size_t)bz * NSS * ND;
    const int NC = ND / 32;

    float acc[2][8][4];
    #pragma unroll
    for (int i = 0; i < 2; ++i)
        #pragma unroll
        for (int j = 0; j < 8; ++j)
            #pragma unroll
            for (int v = 0; v < 4; ++v) acc[i][j][v] = 0.f;

    const int q = lane >> 3, l7 = lane & 7;
    const int ar = rm + ((q & 1) << 3) + l7;
    const int acq = (q >> 1) << 3;
    const int brq = ((q >> 1) << 3) + l7;
    const int bcq = (q & 1) << 3;

    load_stage_g1(Ah, Al, Bh, Bl, m0, n0, 0, sb);
    CP_COMMIT();
    load_stage_g1(Ah, Al, Bh, Bl, m0, n0, 32, sb + STAGE_B);
    CP_COMMIT();

    int buf = 0;
    for (int kc = 0; kc < NC; ++kc) {
        if (kc + 1 < NC) { CP_WAIT(1); } else { CP_WAIT(0); }
        __syncthreads();
        if (kc + 2 < NC) {
            int nbuf = buf + 2; if (nbuf >= 3) nbuf -= 3;
            load_stage_g1(Ah, Al, Bh, Bl, m0, n0, (kc + 2) * 32,
                          sb + (uint32_t)nbuf * STAGE_B);
            CP_COMMIT();
        }
        const uint32_t sbase = sb + (uint32_t)buf * STAGE_B;
        #pragma unroll
        for (int k16 = 0; k16 < 2; ++k16) {
            const int kk = k16 * 16;
            uint32_t A0[4], A1[4], L0[4], L1[4];
            ldsm4(A0, sbase + swz(ar, kk + acq));
            ldsm4(A1, sbase + swz(ar + 16, kk + acq));
            ldsm4(L0, sbase + TILE_B + swz(ar, kk + acq));
            ldsm4(L1, sbase + TILE_B + swz(ar + 16, kk + acq));
            #pragma unroll
            for (int np = 0; np < 4; ++np) {
                uint32_t Bh4[4], Bl4[4];
                const uint32_t boff = swz(cn + np * 16 + brq, kk + bcq);
                ldsm4(Bh4, sbase + 2 * TILE_B + boff);
                ldsm4(Bl4, sbase + 3 * TILE_B + boff);
                hmma_bf(acc[0][2 * np],     A0, Bh4[0], Bh4[1]);
                hmma_bf(acc[0][2 * np + 1], A0, Bh4[2], Bh4[3]);
                hmma_bf(acc[1][2 * np],     A1, Bh4[0], Bh4[1]);
                hmma_bf(acc[1][2 * np + 1], A1, Bh4[2], Bh4[3]);
                hmma_bf(acc[0][2 * np],     A0, Bl4[0], Bl4[1]);
                hmma_bf(acc[0][2 * np + 1], A0, Bl4[2], Bl4[3]);
                hmma_bf(acc[1][2 * np],     A1, Bl4[0], Bl4[1]);
                hmma_bf(acc[1][2 * np + 1], A1, Bl4[2], Bl4[3]);
                hmma_bf(acc[0][2 * np],     L0, Bh4[0], Bh4[1]);
                hmma_bf(acc[0][2 * np + 1], L0, Bh4[2], Bh4[3]);
                hmma_bf(acc[1][2 * np],     L1, Bh4[0], Bh4[1]);
                hmma_bf(acc[1][2 * np + 1], L1, Bh4[2], Bh4[3]);
            }
        }
        if (++buf == 3) buf = 0;
    }

    const int rbase = m0 + rm + (lane >> 2);
    const int cbase = n0 + cn + ((lane & 3) << 1);
    float* dst = g_scores + ((size_t)bz << 20);
    #pragma unroll
    for (int mt = 0; mt < 2; ++mt)
        #pragma unroll
        for (int h = 0; h < 2; ++h) {
            const int row = rbase + mt * 16 + h * 8;
            #pragma unroll
            for (int nt = 0; nt < 8; ++nt)
                *(float2*)(dst + (size_t)row * NSS + cbase + nt * 8) =
                    make_float2(acc[mt][nt][2 * h], acc[mt][nt][2 * h + 1]);
        }
}

// ===========================================================================
// shared loader for 1-term fp16 GEMMs (128x128 tile, K-chunk 32, 4-stage)
// ===========================================================================
static constexpr int STG1T   = 2 * TILE_B;      // A + B = 16 KB
static constexpr int SMEM_1T = 4 * STG1T;       // 64 KB -> 2 CTAs/SM

__device__ __forceinline__ void load_stage_1t(
    const __half* __restrict__ a, const __half* __restrict__ b,
    int lda, int ldb, int m0, int n0, int ka, int kb, uint32_t sbase)
{
    const int tid = threadIdx.x;
    #pragma unroll
    for (int j = 0; j < 2; ++j) {
        const int id = tid + 256 * j;
        const int r  = id >> 2;
        const int c  = (id & 3) << 3;
        const uint32_t off = swz(r, c);
        cpa16(sbase + off,          a + (size_t)(m0 + r) * lda + ka + c);
        cpa16(sbase + TILE_B + off, b + (size_t)(n0 + r) * ldb + kb + c);
    }
}

// ===========================================================================
// GEMM2 (fp16 accumulate): c' = avg @ ctxT^T (K=1024) -> cc_h
// ===========================================================================
__global__ __launch_bounds__(256, 2)
void g2_gemm(const float* __restrict__ wsp)
{
    cudaGridDependencySynchronize();
    extern __shared__ char smem[];
    const uint32_t sb = smem_to_u32(smem);
    const int tid = threadIdx.x;
    const int lane = tid & 31, wid = tid >> 5;
    const int rm = (wid & 3) * 32;
    const int cn = (wid >> 2) * 64;

    const int m0 = blockIdx.y * 128;
    const int n0 = blockIdx.x * 128;
    const int bz = blockIdx.z;

    const __half* A = g_avg_h + (size_t)bz * NTT * NSS;
    const __half* B = g_ctxT_h + (size_t)bz * ND * NSS;
    const int NC = NSS / 32;

    uint32_t acc[2][8][2];
    #pragma unroll
    for (int i = 0; i < 2; ++i)
        #pragma unroll
        for (int j = 0; j < 8; ++j) { acc[i][j][0] = 0u; acc[i][j][1] = 0u; }

    const int q = lane >> 3, l7 = lane & 7;
    const int ar = rm + ((q & 1) << 3) + l7;
    const int acq = (q >> 1) << 3;
    const int brq = ((q >> 1) << 3) + l7;
    const int bcq = (q & 1) << 3;

    load_stage_1t(A, B, NSS, NSS, m0, n0, 0, 0, sb);
    CP_COMMIT();
    load_stage_1t(A, B, NSS, NSS, m0, n0, 32, 32, sb + STG1T);
    CP_COMMIT();

    for (int kc = 0; kc < NC; ++kc) {
        if (kc + 2 < NC) {
            load_stage_1t(A, B, NSS, NSS, m0, n0, (kc + 2) * 32, (kc + 2) * 32,
                          sb + (uint32_t)((kc + 2) & 3) * STG1T);
            CP_COMMIT();
            CP_WAIT(2);
        } else if (kc + 1 < NC) {
            CP_WAIT(1);
        } else {
            CP_WAIT(0);
        }
        __syncthreads();

        const uint32_t sbase = sb + (uint32_t)(kc & 3) * STG1T;
        #pragma unroll
        for (int k16 = 0; k16 < 2; ++k16) {
            const int kk = k16 * 16;
            uint32_t A0[4], A1[4];
            ldsm4(A0, sbase + swz(ar, kk + acq));
            ldsm4(A1, sbase + swz(ar + 16, kk + acq));
            #pragma unroll
            for (int np = 0; np < 4; ++np) {
                uint32_t B4[4];
                ldsm4(B4, sbase + TILE_B + swz(cn + np * 16 + brq, kk + bcq));
                hmma_h16(acc[0][2 * np],     A0, B4[0], B4[1]);
                hmma_h16(acc[0][2 * np + 1], A0, B4[2], B4[3]);
                hmma_h16(acc[1][2 * np],     A1, B4[0], B4[1]);
                hmma_h16(acc[1][2 * np + 1], A1, B4[2], B4[3]);
            }
        }
    }

    const int rbase = m0 + rm + (lane >> 2);
    const int cbase = n0 + cn + ((lane & 3) << 1);
    const float sc = __ldg(wsp) * (1.0f / 1024.0f);
    #pragma unroll
    for (int mt = 0; mt < 2; ++mt)
        #pragma unroll
        for (int h = 0; h < 2; ++h) {
            const int row = rbase + mt * 16 + h * 8;
            __half* dst = g_cc_h + ((size_t)bz * NTT + row) * ND;
            #pragma unroll
            for (int nt = 0; nt < 8; ++nt) {
                const float2 f = __half22float2(*(__half2*)&acc[mt][nt][h]);
                *(__half2*)(dst + cbase + nt * 8) =
                    __floats2half2_rn(f.x * sc, f.y * sc);
            }
        }
}

// ===========================================================================
// GEMM3 (fp32 accumulate): h = [cc;inp_h] @ w_h^T + bias2, PReLU -> out1
// ===========================================================================
__global__ __launch_bounds__(256, 2)
void g3_gemm(const float* __restrict__ pap, float* __restrict__ out1)
{
    cudaGridDependencySynchronize();
    extern __shared__ char smem[];
    const uint32_t sb = smem_to_u32(smem);
    const int tid = threadIdx.x;
    const int lane = tid & 31, wid = tid >> 5;
    const int rm = (wid & 3) * 32;
    const int cn = (wid >> 2) * 64;

    const int m0 = blockIdx.y * 128;
    const int n0 = blockIdx.x * 128;

    const __half* A = g_cc_h;
    const __half* B = g_w_h;
    const int NC = NK3 / 32;

    float acc[2][8][4];
    #pragma unroll
    for (int i = 0; i < 2; ++i)
        #pragma unroll
        for (int j = 0; j < 8; ++j)
            #pragma unroll
            for (int v = 0; v < 4; ++v) acc[i][j][v] = 0.f;

    const int q = lane >> 3, l7 = lane & 7;
    const int ar = rm + ((q & 1) << 3) + l7;
    const int acq = (q >> 1) << 3;
    const int brq = ((q >> 1) << 3) + l7;
    const int bcq = (q & 1) << 3;

    load_stage_1t(A, B, ND, NK3, m0, n0, 0, 0, sb);
    CP_COMMIT();
    load_stage_1t(A, B, ND, NK3, m0, n0, 32, 32, sb + STG1T);
    CP_COMMIT();

    for (int kc = 0; kc < NC; ++kc) {
        if (kc + 2 < NC) {
            const __half* a = A;
            int ka = (kc + 2) * 32;
            const int kb = ka;
            if (ka >= ND) { a = g_inp_h; ka -= ND; }
            load_stage_1t(a, B, ND, NK3, m0, n0, ka, kb,
                          sb + (uint32_t)((kc + 2) & 3) * STG1T);
            CP_COMMIT();
            CP_WAIT(2);
        } else if (kc + 1 < NC) {
            CP_WAIT(1);
        } else {
            CP_WAIT(0);
        }
        __syncthreads();

        const uint32_t sbase = sb + (uint32_t)(kc & 3) * STG1T;
        #pragma unroll
        for (int k16 = 0; k16 < 2; ++k16) {
            const int kk = k16 * 16;
            uint32_t A0[4], A1[4];
            ldsm4(A0, sbase + swz(ar, kk + acq));
            ldsm4(A1, sbase + swz(ar + 16, kk + acq));
            #pragma unroll
            for (int np = 0; np < 4; ++np) {
                uint32_t B4[4];
                ldsm4(B4, sbase + TILE_B + swz(cn + np * 16 + brq, kk + bcq));
                hmma_f16(acc[0][2 * np],     A0, B4[0], B4[1]);
                hmma_f16(acc[0][2 * np + 1], A0, B4[2], B4[3]);
                hmma_f16(acc[1][2 * np],     A1, B4[0], B4[1]);
                hmma_f16(acc[1][2 * np + 1], A1, B4[2], B4[3]);
            }
        }
    }

    const int rbase = m0 + rm + (lane >> 2);
    const int cbase = n0 + cn + ((lane & 3) << 1);
    const float pa = __ldg(pap);
    #pragma unroll
    for (int mt = 0; mt < 2; ++mt)
        #pragma unroll
        for (int h = 0; h < 2; ++h) {
            const int row = rbase + mt * 16 + h * 8;
            const int bb = row >> 10, tt = row & 1023;
            float* dst = out1 + ((size_t)tt * NB + bb) * ND;
            #pragma unroll
            for (int nt = 0; nt < 8; ++nt) {
                const int col = cbase + nt * 8;
                float v0 = acc[mt][nt][2 * h]     + __ldg(&g_bias2[col]);
                float v1 = acc[mt][nt][2 * h + 1] + __ldg(&g_bias2[col + 1]);
                v0 = (v0 >= 0.f) ? v0 : pa * v0;
                v1 = (v1 >= 0.f) ? v1 : pa * v1;
                *(float2*)(dst + col) = make_float2(v0, v1);
            }
        }
}

// ---------------------------------------------------------------------------
// fused inp prep + W prep (merged grids)
// ---------------------------------------------------------------------------
static constexpr int NIB = NB * NTT * ND / 4 / 256;   // 12288

__global__ __launch_bounds__(256)
void fuse_inp(const float* __restrict__ src, const float* __restrict__ W,
              const float* __restrict__ bo, const float* __restrict__ bsp)
{
    __shared__ float red[8];
    if (blockIdx.x >= NIB) {
        const int n = blockIdx.x - NIB;
        const int tid = threadIdx.x;
        float sum = 0.f;
        #pragma unroll
        for (int k0 = 0; k0 < NK3; k0 += 1024) {
            const int k = k0 + tid * 4;
            float4 v = *(const float4*)(W + (size_t)n * NK3 + k);
            ((__half2*)(g_w_h + (size_t)n * NK3 + k))[0] = __floats2half2_rn(v.x, v.y);
            ((__half2*)(g_w_h + (size_t)n * NK3 + k))[1] = __floats2half2_rn(v.z, v.w);
            if (k < ND) sum += (v.x + v.y) + (v.z + v.w);
        }
        #pragma unroll
        for (int o = 16; o; o >>= 1) sum += __shfl_xor_sync(0xffffffffu, sum, o);
        if ((tid & 31) == 0) red[tid >> 5] = sum;
        __syncthreads();
        if (tid == 0) {
            float t = ((red[0] + red[1]) + (red[2] + red[3])) +
                      ((red[4] + red[5]) + (red[6] + red[7]));
            g_bias2[n] = __ldg(bsp) * t + __ldg(bo + n);
        }
        return;
    }
    const size_t i = (size_t)blockIdx.x * 256 + threadIdx.x;
    float4 v = ((const float4*)src)[i];
    __nv_bfloat16 h0 = __float2bfloat16(v.x), h1 = __float2bfloat16(v.y);
    __nv_bfloat16 h2 = __float2bfloat16(v.z), h3 = __float2bfloat16(v.w);
    __nv_bfloat16 l0 = __float2bfloat16(v.x - __bfloat162float(h0));
    __nv_bfloat16 l1 = __float2bfloat16(v.y - __bfloat162float(h1));
    __nv_bfloat16 l2 = __float2bfloat16(v.z - __bfloat162float(h2));
    __nv_bfloat16 l3 = __float2bfloat16(v.w - __bfloat162float(h3));
    ((__nv_bfloat162*)g_inp_hi)[2 * i]     = __halves2bfloat162(h0, h1);
    ((__nv_bfloat162*)g_inp_hi)[2 * i + 1] = __halves2bfloat162(h2, h3);
    ((__nv_bfloat162*)g_inp_lo)[2 * i]     = __halves2bfloat162(l0, l1);
    ((__nv_bfloat162*)g_inp_lo)[2 * i + 1] = __halves2bfloat162(l2, l3);
    ((__half2*)g_inp_h)[2 * i]     = __floats2half2_rn(v.x, v.y);
    ((__half2*)g_inp_h)[2 * i + 1] = __floats2half2_rn(v.z, v.w);
}

// ---------------------------------------------------------------------------
// fused ctx prep (vectorized): 64s x 64d tile per block
// ---------------------------------------------------------------------------
__global__ __launch_bounds__(256)
void fuse_ctx(const float* __restrict__ ctx)
{
    cudaGridDependencySynchronize();
    __shared__ float ts[64][65];
    const int b = blockIdx.z;
    const int d0 = blockIdx.x * 64;
    const int s0 = blockIdx.y * 64;
    const int tx = threadIdx.x, ty = threadIdx.y;   // 32 x 8
    #pragma unroll
    for (int r = ty; r < 64; r += 8) {
        const float2 v = *(const float2*)(ctx + (size_t)b * NSS * ND
                                          + (size_t)(s0 + r) * ND + d0 + 2 * tx);
        ts[r][2 * tx]     = v.x;
        ts[r][2 * tx + 1] = v.y;
        __nv_bfloat16 h0 = __float2bfloat16(v.x);
        __nv_bfloat16 h1 = __float2bfloat16(v.y);
        __nv_bfloat16 l0 = __float2bfloat16(v.x - __bfloat162float(h0));
        __nv_bfloat16 l1 = __float2bfloat16(v.y - __bfloat162float(h1));
        const size_t o = ((size_t)b * NSS + s0 + r) * ND + d0 + 2 * tx;
        *(__nv_bfloat162*)(g_ctx_hi + o) = __halves2bfloat162(h0, h1);
        *(__nv_bfloat162*)(g_ctx_lo + o) = __halves2bfloat162(l0, l1);
    }
    __syncthreads();
    #pragma unroll
    for (int r = ty; r < 64; r += 8) {
        float v0 = ts[2 * tx][r];
        float v1 = ts[2 * tx + 1][r];
        const size_t o = (size_t)b * ND * NSS + (size_t)(d0 + r) * NSS + s0 + 2 * tx;
        *(__half2*)(g_ctxT_h + o) = __floats2half2_rn(v0, v1);
    }
}

// ---------------------------------------------------------------------------
// row softmax over S: reads fp32 logits, writes fp16 av (fast exp)
// ---------------------------------------------------------------------------
__global__ __launch_bounds__(256)
void softmax_k()
{
    cudaGridDependencySynchronize();
    const float* row = g_scores + (size_t)blockIdx.x * NSS;
    const int tid = threadIdx.x;
    const unsigned FULL = 0xffffffffu;
    float4 x = *(const float4*)(row + tid * 4);
    float m = fmaxf(fmaxf(x.x, x.y), fmaxf(x.z, x.w));
    __shared__ float sred[8];
    __shared__ float sred2[8];
    #pragma unroll
    for (int o = 16; o; o >>= 1) m = fmaxf(m, __shfl_xor_sync(FULL, m, o));
    if ((tid & 31) == 0) sred[tid >> 5] = m;
    __syncthreads();
    m = fmaxf(fmaxf(fmaxf(sred[0], sred[1]), fmaxf(sred[2], sred[3])),
              fmaxf(fmaxf(sred[4], sred[5]), fmaxf(sred[6], sred[7])));
    float e0 = __expf(x.x - m), e1 = __expf(x.y - m);
    float e2 = __expf(x.z - m), e3 = __expf(x.w - m);
    float s = (e0 + e1) + (e2 + e3);
    #pragma unroll
    for (int o = 16; o; o >>= 1) s += __shfl_xor_sync(FULL, s, o);
    if ((tid & 31) == 0) sred2[tid >> 5] = s;
    __syncthreads();
    s = ((sred2[0] + sred2[1]) + (sred2[2] + sred2[3])) +
        ((sred2[4] + sred2[5]) + (sred2[6] + sred2[7]));
    const float inv = 1.0f / s;
    __half* dst = g_av_h + (size_t)blockIdx.x * NSS + tid * 4;
    *(__half2*)(dst)     = __floats2half2_rn(e0 * inv, e1 * inv);
    *(__half2*)(dst + 2) = __floats2half2_rn(e2 * inv, e3 * inv);
}

// ---------------------------------------------------------------------------
// gate, phase 1: partial column sums over 128-row chunks (fp16 input)
// ---------------------------------------------------------------------------
__global__ __launch_bounds__(256)
void gate_part()
{
    cudaGridDependencySynchronize();
    const int s2 = blockIdx.x * 512 + threadIdx.x * 2;
    const int tc = blockIdx.y;
    const int b = blockIdx.z;
    const __half* p = g_av_h + (size_t)b * NTT * NSS + (size_t)tc * 128 * NSS + s2;
    float2 a0 = {0.f, 0.f}, a1 = {0.f, 0.f}, a2 = {0.f, 0.f}, a3 = {0.f, 0.f};
    #pragma unroll
    for (int t = 0; t < 128; t += 4) {
        float2 f0 = __half22float2(*(const __half2*)(p + (size_t)(t + 0) * NSS));
        float2 f1 = __half22float2(*(const __half2*)(p + (size_t)(t + 1) * NSS));
        float2 f2 = __half22float2(*(const __half2*)(p + (size_t)(t + 2) * NSS));
        float2 f3 = __half22float2(*(const __half2*)(p + (size_t)(t + 3) * NSS));
        a0.x += f0.x; a0.y += f0.y;
        a1.x += f1.x; a1.y += f1.y;
        a2.x += f2.x; a2.y += f2.y;
        a3.x += f3.x; a3.y += f3.y;
    }
    float2 r;
    r.x = (a0.x + a1.x) + (a2.x + a3.x);
    r.y = (a0.y + a1.y) + (a2.y + a3.y);
    *(float2*)(&g_gpart[tc][b * NSS + s2]) = r;
}

// gate, phase 2: reduce 8 partials + sigmoid
__global__ __launch_bounds__(256)
void gate_fin()
{
    cudaGridDependencySynchronize();
    const int gid = blockIdx.x * 256 + threadIdx.x;
    float s = 0.f;
    #pragma unroll
    for (int i = 0; i < 8; ++i) s += g_gpart[i][gid];
    g_gate[gid] = 1.0f / (1.0f + __expf(-s));
}

// ---------------------------------------------------------------------------
// av_g: reads fp16 av; out2 [T,B,S] = av*gate/1024 (fp32);
//       g_avg_h [B,T,S] = fp16(av*gate)
// ---------------------------------------------------------------------------
__global__ __launch_bounds__(256)
void avg_k(float* __restrict__ out2)
{
    cudaGridDependencySynchronize();
    const int bt = blockIdx.x;
    const int b = bt >> 10, t = bt & 1023;
    const int s = threadIdx.x * 4;
    const __half* src = g_av_h + (size_t)bt * NSS + s;
    float2 f01 = __half22float2(*(const __half2*)(src));
    float2 f23 = __half22float2(*(const __half2*)(src + 2));
    float4 g = *(const float4*)(g_gate + b * NSS + s);
    float4 v;
    v.x = f01.x * g.x; v.y = f01.y * g.y; v.z = f23.x * g.z; v.w = f23.y * g.w;
    const float pool = 1.0f / 1024.0f;
    *(float4*)(out2 + ((size_t)t * NB + b) * NSS + s) =
        make_float4(v.x * pool, v.y * pool, v.z * pool, v.w * pool);
    __half2* ph = (__half2*)(g_avg_h + (size_t)bt * NSS + s);
    ph[0] = __floats2half2_rn(v.x, v.y);
    ph[1] = __floats2half2_rn(v.z, v.w);
}

// ---------------------------------------------------------------------------
// PDL launch helper: programmatic stream serialization on the legacy stream
// ---------------------------------------------------------------------------
#define LAUNCH_PDL(kern, grid, block, smem, ...) do {                         \
    cudaLaunchConfig_t _cfg = {};                                             \
    cudaLaunchAttribute _at[1];                                               \
    _at[0].id = cudaLaunchAttributeProgrammaticStreamSerialization;           \
    _at[0].val.programmaticStreamSerializationAllowed = 1;                    \
    _cfg.gridDim = grid; _cfg.blockDim = block;                               \
    _cfg.dynamicSmemBytes = smem; _cfg.stream = 0;                            \
    _cfg.attrs = _at; _cfg.numAttrs = 1;                                      \
    cudaLaunchKernelEx(&_cfg, kern, ##__VA_ARGS__);                           \
} while (0)

extern "C" void kernel_launch(void* const* d_in, const int* in_sizes, int n_in,
                              void* d_out, int out_size)
{
    const float* inp = (const float*)d_in[0];   // [B,T,768]
    const float* ctx = (const float*)d_in[1];   // [B,S,768]
    const float* W   = (const float*)d_in[2];   // [768,1536]
    const float* bo  = (const float*)d_in[3];   // [768]
    const float* ws  = (const float*)d_in[4];   // [1]
    const float* bs  = (const float*)d_in[5];   // [1]
    const float* pa  = (const float*)d_in[6];   // [1]
    float* out1 = (float*)d_out;                          // attn_h^T [T,B,768]
    float* out2 = out1 + (size_t)NTT * NB * ND;           // av_g^T   [T,B,S]

    cudaFuncSetAttribute(g1_gemm, cudaFuncAttributeMaxDynamicSharedMemorySize, SMEM_G1);
    cudaFuncSetAttribute(g2_gemm, cudaFuncAttributeMaxDynamicSharedMemorySize, SMEM_1T);
    cudaFuncSetAttribute(g3_gemm, cudaFuncAttributeMaxDynamicSharedMemorySize, SMEM_1T);

    fuse_inp<<<NIB + ND, 256>>>(inp, W, bo, bs);
    LAUNCH_PDL(fuse_ctx, dim3(ND / 64, NSS / 64, NB), dim3(32, 8), 0, ctx);
    LAUNCH_PDL(g1_gemm, dim3(8, 8, NB), dim3(256), SMEM_G1);
    LAUNCH_PDL(softmax_k, dim3(NB * NTT), dim3(256), 0);
    LAUNCH_PDL(gate_part, dim3(2, 8, NB), dim3(256), 0);
    LAUNCH_PDL(gate_fin, dim3(NB * NSS / 256), dim3(256), 0);
    LAUNCH_PDL(avg_k, dim3(NB * NTT), dim3(256), 0, out2);
    LAUNCH_PDL(g2_gemm, dim3(6, 8, NB), dim3(256), SMEM_1T, ws);
    LAUNCH_PDL(g3_gemm, dim3(6, 128, 1), dim3(256), SMEM_1T, pa, out1);
}

// round 17
// speedup vs baseline: 1.1415x; 1.0009x over previous
#include <cuda_runtime.h>
#include <cuda_bf16.h>
#include <cuda_fp16.h>
#include <stdint.h>
#include <math.h>

#define NB 16
#define NTT 1024
#define NSS 1024
#define ND 768
#define NK3 1536

// ---------------------------------------------------------------------------
// scratch (static device globals — no allocations allowed)
// ---------------------------------------------------------------------------
__device__ float g_scores[(size_t)NB * NTT * NSS];         // G1 logits (fp32)
__device__ __half g_av_h[(size_t)NB * NTT * NSS];          // softmax result (fp16)
__device__ float g_gate[NB * NSS];
__device__ float g_gpart[8][NB * NSS];
__device__ float g_bias2[ND];
__device__ __nv_bfloat16 g_inp_hi[(size_t)NB * NTT * ND];  // GEMM1 A (3-term)
__device__ __nv_bfloat16 g_inp_lo[(size_t)NB * NTT * ND];
__device__ __nv_bfloat16 g_ctx_hi[(size_t)NB * NSS * ND];  // GEMM1 B (3-term)
__device__ __nv_bfloat16 g_ctx_lo[(size_t)NB * NSS * ND];
__device__ __half g_inp_h[(size_t)NB * NTT * ND];          // GEMM3 A part2
__device__ __half g_ctxT_h[(size_t)NB * ND * NSS];         // GEMM2 B
__device__ __half g_avg_h[(size_t)NB * NTT * NSS];         // GEMM2 A (av*gate)
__device__ __half g_cc_h[(size_t)NB * NTT * ND];           // GEMM3 A part1 (c*ws/1024)
__device__ __half g_w_h[ND * NK3];                         // GEMM3 B

// ---------------------------------------------------------------------------
// sm_80-compatible PTX helpers (NO tcgen05 — harness targets compute_103)
// ---------------------------------------------------------------------------
__device__ __forceinline__ uint32_t smem_to_u32(const void* p) {
    uint32_t a;
    asm("{ .reg .u64 t; cvta.to.shared.u64 t, %1; cvt.u32.u64 %0, t; }" : "=r"(a) : "l"(p));
    return a;
}

__device__ __forceinline__ void cpa16(uint32_t dst, const void* src) {
    asm volatile("cp.async.cg.shared.global [%0], [%1], 16;" :: "r"(dst), "l"(src));
}
#define CP_COMMIT() asm volatile("cp.async.commit_group;" ::: "memory")
#define CP_WAIT(n)  asm volatile("cp.async.wait_group %0;" :: "n"(n) : "memory")

__device__ __forceinline__ void ldsm4(uint32_t (&r)[4], uint32_t addr) {
    asm volatile("ldmatrix.sync.aligned.m8n8.x4.shared.b16 {%0,%1,%2,%3}, [%4];"
                 : "=r"(r[0]), "=r"(r[1]), "=r"(r[2]), "=r"(r[3]) : "r"(addr));
}

__device__ __forceinline__ void hmma_bf(float (&d)[4], const uint32_t (&a)[4],
                                        uint32_t b0, uint32_t b1) {
    asm volatile(
        "mma.sync.aligned.m16n8k16.row.col.f32.bf16.bf16.f32 "
        "{%0,%1,%2,%3}, {%4,%5,%6,%7}, {%8,%9}, {%0,%1,%2,%3};"
        : "+f"(d[0]), "+f"(d[1]), "+f"(d[2]), "+f"(d[3])
        : "r"(a[0]), "r"(a[1]), "r"(a[2]), "r"(a[3]), "r"(b0), "r"(b1));
}

__device__ __forceinline__ void hmma_f16(float (&d)[4], const uint32_t (&a)[4],
                                         uint32_t b0, uint32_t b1) {
    asm volatile(
        "mma.sync.aligned.m16n8k16.row.col.f32.f16.f16.f32 "
        "{%0,%1,%2,%3}, {%4,%5,%6,%7}, {%8,%9}, {%0,%1,%2,%3};"
        : "+f"(d[0]), "+f"(d[1]), "+f"(d[2]), "+f"(d[3])
        : "r"(a[0]), "r"(a[1]), "r"(a[2]), "r"(a[3]), "r"(b0), "r"(b1));
}

// fp16-accumulate variant (GEMM2)
__device__ __forceinline__ void hmma_h16(uint32_t (&d)[2], const uint32_t (&a)[4],
                                         uint32_t b0, uint32_t b1) {
    asm volatile(
        "mma.sync.aligned.m16n8k16.row.col.f16.f16.f16.f16 "
        "{%0,%1}, {%2,%3,%4,%5}, {%6,%7}, {%0,%1};"
        : "+r"(d[0]), "+r"(d[1])
        : "r"(a[0]), "r"(a[1]), "r"(a[2]), "r"(a[3]), "r"(b0), "r"(b1));
}

// byte offset of 16-bit elem (r, c) inside a 128x32 SW64-swizzled tile (64B rows)
__device__ __forceinline__ uint32_t swz(int r, int c) {
    int off = (r << 6) + (c << 1);
    return (uint32_t)(off ^ ((off >> 3) & 0x30));
}

// ===========================================================================
// GEMM1: bf16 3-term split (AhBh + AhBl + AlBh), 128x128 tile, K-chunk 32
// ===========================================================================
static constexpr int TILE_B   = 8192;        // one 128x32 16-bit tile (SW64)
static constexpr int STAGE_B  = 4 * TILE_B;  // Ah, Al, Bh, Bl = 32 KB
static constexpr int SMEM_G1  = 3 * STAGE_B; // 96 KB -> 2 CTAs/SM

__device__ __forceinline__ void load_stage_g1(
    const __nv_bfloat16* __restrict__ ah, const __nv_bfloat16* __restrict__ al,
    const __nv_bfloat16* __restrict__ bh, const __nv_bfloat16* __restrict__ bl,
    int m0, int n0, int k0, uint32_t sbase)
{
    const int tid = threadIdx.x;
    #pragma unroll
    for (int j = 0; j < 2; ++j) {
        const int id = tid + 256 * j;
        const int r  = id >> 2;
        const int c  = (id & 3) << 3;
        const uint32_t off = swz(r, c);
        cpa16(sbase + off,              ah + (size_t)(m0 + r) * ND + k0 + c);
        cpa16(sbase + TILE_B + off,     al + (size_t)(m0 + r) * ND + k0 + c);
        cpa16(sbase + 2 * TILE_B + off, bh + (size_t)(n0 + r) * ND + k0 + c);
        cpa16(sbase + 3 * TILE_B + off, bl + (size_t)(n0 + r) * ND + k0 + c);
    }
}

__global__ __launch_bounds__(256, 2)
void g1_gemm()
{
    cudaGridDependencySynchronize();
    extern __shared__ char smem[];
    const uint32_t sb = smem_to_u32(smem);
    const int tid = threadIdx.x;
    const int lane = tid & 31, wid = tid >> 5;
    const int rm = (wid & 3) * 32;
    const int cn = (wid >> 2) * 64;

    const int m0 = blockIdx.y * 128;
    const int n0 = blockIdx.x * 128;
    const int bz = blockIdx.z;

    const __nv_bfloat16* Ah = g_inp_hi + (size_t)bz * NTT * ND;
    const __nv_bfloat16* Al = g_inp_lo + (size_t)bz * NTT * ND;
    const __nv_bfloat16* Bh = g_ctx_hi + (size_t)bz * NSS * ND;
    const __nv_bfloat16* Bl = g_ctx_lo + (size_t)bz * NSS * ND;
    const int NC = ND / 32;

    float acc[2][8][4];
    #pragma unroll
    for (int i = 0; i < 2; ++i)
        #pragma unroll
        for (int j = 0; j < 8; ++j)
            #pragma unroll
            for (int v = 0; v < 4; ++v) acc[i][j][v] = 0.f;

    const int q = lane >> 3, l7 = lane & 7;
    const int ar = rm + ((q & 1) << 3) + l7;
    const int acq = (q >> 1) << 3;
    const int brq = ((q >> 1) << 3) + l7;
    const int bcq = (q & 1) << 3;

    load_stage_g1(Ah, Al, Bh, Bl, m0, n0, 0, sb);
    CP_COMMIT();
    load_stage_g1(Ah, Al, Bh, Bl, m0, n0, 32, sb + STAGE_B);
    CP_COMMIT();

    int buf = 0;
    for (int kc = 0; kc < NC; ++kc) {
        if (kc + 1 < NC) { CP_WAIT(1); } else { CP_WAIT(0); }
        __syncthreads();
        if (kc + 2 < NC) {
            int nbuf = buf + 2; if (nbuf >= 3) nbuf -= 3;
            load_stage_g1(Ah, Al, Bh, Bl, m0, n0, (kc + 2) * 32,
                          sb + (uint32_t)nbuf * STAGE_B);
            CP_COMMIT();
        }
        const uint32_t sbase = sb + (uint32_t)buf * STAGE_B;
        #pragma unroll
        for (int k16 = 0; k16 < 2; ++k16) {
            const int kk = k16 * 16;
            uint32_t A0[4], A1[4], L0[4], L1[4];
            ldsm4(A0, sbase + swz(ar, kk + acq));
            ldsm4(A1, sbase + swz(ar + 16, kk + acq));
            ldsm4(L0, sbase + TILE_B + swz(ar, kk + acq));
            ldsm4(L1, sbase + TILE_B + swz(ar + 16, kk + acq));
            #pragma unroll
            for (int np = 0; np < 4; ++np) {
                uint32_t Bh4[4], Bl4[4];
                const uint32_t boff = swz(cn + np * 16 + brq, kk + bcq);
                ldsm4(Bh4, sbase + 2 * TILE_B + boff);
                ldsm4(Bl4, sbase + 3 * TILE_B + boff);
                hmma_bf(acc[0][2 * np],     A0, Bh4[0], Bh4[1]);
                hmma_bf(acc[0][2 * np + 1], A0, Bh4[2], Bh4[3]);
                hmma_bf(acc[1][2 * np],     A1, Bh4[0], Bh4[1]);
                hmma_bf(acc[1][2 * np + 1], A1, Bh4[2], Bh4[3]);
                hmma_bf(acc[0][2 * np],     A0, Bl4[0], Bl4[1]);
                hmma_bf(acc[0][2 * np + 1], A0, Bl4[2], Bl4[3]);
                hmma_bf(acc[1][2 * np],     A1, Bl4[0], Bl4[1]);
                hmma_bf(acc[1][2 * np + 1], A1, Bl4[2], Bl4[3]);
                hmma_bf(acc[0][2 * np],     L0, Bh4[0], Bh4[1]);
                hmma_bf(acc[0][2 * np + 1], L0, Bh4[2], Bh4[3]);
                hmma_bf(acc[1][2 * np],     L1, Bh4[0], Bh4[1]);
                hmma_bf(acc[1][2 * np + 1], L1, Bh4[2], Bh4[3]);
            }
        }
        if (++buf == 3) buf = 0;
    }

    const int rbase = m0 + rm + (lane >> 2);
    const int cbase = n0 + cn + ((lane & 3) << 1);
    float* dst = g_scores + ((size_t)bz << 20);
    #pragma unroll
    for (int mt = 0; mt < 2; ++mt)
        #pragma unroll
        for (int h = 0; h < 2; ++h) {
            const int row = rbase + mt * 16 + h * 8;
            #pragma unroll
            for (int nt = 0; nt < 8; ++nt)
                *(float2*)(dst + (size_t)row * NSS + cbase + nt * 8) =
                    make_float2(acc[mt][nt][2 * h], acc[mt][nt][2 * h + 1]);
        }
}

// ===========================================================================
// shared loader for 1-term fp16 GEMMs (128x128 tile, K-chunk 32, 4-stage)
// ===========================================================================
static constexpr int STG1T   = 2 * TILE_B;      // A + B = 16 KB
static constexpr int SMEM_1T = 4 * STG1T;       // 64 KB -> 2 CTAs/SM

__device__ __forceinline__ void load_stage_1t(
    const __half* __restrict__ a, const __half* __restrict__ b,
    int lda, int ldb, int m0, int n0, int ka, int kb, uint32_t sbase)
{
    const int tid = threadIdx.x;
    #pragma unroll
    for (int j = 0; j < 2; ++j) {
        const int id = tid + 256 * j;
        const int r  = id >> 2;
        const int c  = (id & 3) << 3;
        const uint32_t off = swz(r, c);
        cpa16(sbase + off,          a + (size_t)(m0 + r) * lda + ka + c);
        cpa16(sbase + TILE_B + off, b + (size_t)(n0 + r) * ldb + kb + c);
    }
}

// ===========================================================================
// GEMM2 (fp16 accumulate): c' = avg @ ctxT^T (K=1024) -> cc_h
// ===========================================================================
__global__ __launch_bounds__(256, 2)
void g2_gemm(const float* __restrict__ wsp)
{
    cudaGridDependencySynchronize();
    extern __shared__ char smem[];
    const uint32_t sb = smem_to_u32(smem);
    const int tid = threadIdx.x;
    const int lane = tid & 31, wid = tid >> 5;
    const int rm = (wid & 3) * 32;
    const int cn = (wid >> 2) * 64;

    const int m0 = blockIdx.y * 128;
    const int n0 = blockIdx.x * 128;
    const int bz = blockIdx.z;

    const __half* A = g_avg_h + (size_t)bz * NTT * NSS;
    const __half* B = g_ctxT_h + (size_t)bz * ND * NSS;
    const int NC = NSS / 32;

    uint32_t acc[2][8][2];
    #pragma unroll
    for (int i = 0; i < 2; ++i)
        #pragma unroll
        for (int j = 0; j < 8; ++j) { acc[i][j][0] = 0u; acc[i][j][1] = 0u; }

    const int q = lane >> 3, l7 = lane & 7;
    const int ar = rm + ((q & 1) << 3) + l7;
    const int acq = (q >> 1) << 3;
    const int brq = ((q >> 1) << 3) + l7;
    const int bcq = (q & 1) << 3;

    load_stage_1t(A, B, NSS, NSS, m0, n0, 0, 0, sb);
    CP_COMMIT();
    load_stage_1t(A, B, NSS, NSS, m0, n0, 32, 32, sb + STG1T);
    CP_COMMIT();

    for (int kc = 0; kc < NC; ++kc) {
        if (kc + 2 < NC) {
            load_stage_1t(A, B, NSS, NSS, m0, n0, (kc + 2) * 32, (kc + 2) * 32,
                          sb + (uint32_t)((kc + 2) & 3) * STG1T);
            CP_COMMIT();
            CP_WAIT(2);
        } else if (kc + 1 < NC) {
            CP_WAIT(1);
        } else {
            CP_WAIT(0);
        }
        __syncthreads();

        const uint32_t sbase = sb + (uint32_t)(kc & 3) * STG1T;
        #pragma unroll
        for (int k16 = 0; k16 < 2; ++k16) {
            const int kk = k16 * 16;
            uint32_t A0[4], A1[4];
            ldsm4(A0, sbase + swz(ar, kk + acq));
            ldsm4(A1, sbase + swz(ar + 16, kk + acq));
            #pragma unroll
            for (int np = 0; np < 4; ++np) {
                uint32_t B4[4];
                ldsm4(B4, sbase + TILE_B + swz(cn + np * 16 + brq, kk + bcq));
                hmma_h16(acc[0][2 * np],     A0, B4[0], B4[1]);
                hmma_h16(acc[0][2 * np + 1], A0, B4[2], B4[3]);
                hmma_h16(acc[1][2 * np],     A1, B4[0], B4[1]);
                hmma_h16(acc[1][2 * np + 1], A1, B4[2], B4[3]);
            }
        }
    }

    const int rbase = m0 + rm + (lane >> 2);
    const int cbase = n0 + cn + ((lane & 3) << 1);
    const float sc = __ldg(wsp) * (1.0f / 1024.0f);
    #pragma unroll
    for (int mt = 0; mt < 2; ++mt)
        #pragma unroll
        for (int h = 0; h < 2; ++h) {
            const int row = rbase + mt * 16 + h * 8;
            __half* dst = g_cc_h + ((size_t)bz * NTT + row) * ND;
            #pragma unroll
            for (int nt = 0; nt < 8; ++nt) {
                const float2 f = __half22float2(*(__half2*)&acc[mt][nt][h]);
                *(__half2*)(dst + cbase + nt * 8) =
                    __floats2half2_rn(f.x * sc, f.y * sc);
            }
        }
}

// ===========================================================================
// GEMM3 (fp32 accumulate): h = [cc;inp_h] @ w_h^T + bias2, PReLU -> out1
// ===========================================================================
__global__ __launch_bounds__(256, 2)
void g3_gemm(const float* __restrict__ pap, float* __restrict__ out1)
{
    cudaGridDependencySynchronize();
    extern __shared__ char smem[];
    const uint32_t sb = smem_to_u32(smem);
    const int tid = threadIdx.x;
    const int lane = tid & 31, wid = tid >> 5;
    const int rm = (wid & 3) * 32;
    const int cn = (wid >> 2) * 64;

    const int m0 = blockIdx.y * 128;
    const int n0 = blockIdx.x * 128;

    const __half* A = g_cc_h;
    const __half* B = g_w_h;
    const int NC = NK3 / 32;

    float acc[2][8][4];
    #pragma unroll
    for (int i = 0; i < 2; ++i)
        #pragma unroll
        for (int j = 0; j < 8; ++j)
            #pragma unroll
            for (int v = 0; v < 4; ++v) acc[i][j][v] = 0.f;

    const int q = lane >> 3, l7 = lane & 7;
    const int ar = rm + ((q & 1) << 3) + l7;
    const int acq = (q >> 1) << 3;
    const int brq = ((q >> 1) << 3) + l7;
    const int bcq = (q & 1) << 3;

    load_stage_1t(A, B, ND, NK3, m0, n0, 0, 0, sb);
    CP_COMMIT();
    load_stage_1t(A, B, ND, NK3, m0, n0, 32, 32, sb + STG1T);
    CP_COMMIT();

    for (int kc = 0; kc < NC; ++kc) {
        if (kc + 2 < NC) {
            const __half* a = A;
            int ka = (kc + 2) * 32;
            const int kb = ka;
            if (ka >= ND) { a = g_inp_h; ka -= ND; }
            load_stage_1t(a, B, ND, NK3, m0, n0, ka, kb,
                          sb + (uint32_t)((kc + 2) & 3) * STG1T);
            CP_COMMIT();
            CP_WAIT(2);
        } else if (kc + 1 < NC) {
            CP_WAIT(1);
        } else {
            CP_WAIT(0);
        }
        __syncthreads();

        const uint32_t sbase = sb + (uint32_t)(kc & 3) * STG1T;
        #pragma unroll
        for (int k16 = 0; k16 < 2; ++k16) {
            const int kk = k16 * 16;
            uint32_t A0[4], A1[4];
            ldsm4(A0, sbase + swz(ar, kk + acq));
            ldsm4(A1, sbase + swz(ar + 16, kk + acq));
            #pragma unroll
            for (int np = 0; np < 4; ++np) {
                uint32_t B4[4];
                ldsm4(B4, sbase + TILE_B + swz(cn + np * 16 + brq, kk + bcq));
                hmma_f16(acc[0][2 * np],     A0, B4[0], B4[1]);
                hmma_f16(acc[0][2 * np + 1], A0, B4[2], B4[3]);
                hmma_f16(acc[1][2 * np],     A1, B4[0], B4[1]);
                hmma_f16(acc[1][2 * np + 1], A1, B4[2], B4[3]);
            }
        }
    }

    const int rbase = m0 + rm + (lane >> 2);
    const int cbase = n0 + cn + ((lane & 3) << 1);
    const float pa = __ldg(pap);
    #pragma unroll
    for (int mt = 0; mt < 2; ++mt)
        #pragma unroll
        for (int h = 0; h < 2; ++h) {
            const int row = rbase + mt * 16 + h * 8;
            const int bb = row >> 10, tt = row & 1023;
            float* dst = out1 + ((size_t)tt * NB + bb) * ND;
            #pragma unroll
            for (int nt = 0; nt < 8; ++nt) {
                const int col = cbase + nt * 8;
                float v0 = acc[mt][nt][2 * h]     + __ldg(&g_bias2[col]);
                float v1 = acc[mt][nt][2 * h + 1] + __ldg(&g_bias2[col + 1]);
                v0 = (v0 >= 0.f) ? v0 : pa * v0;
                v1 = (v1 >= 0.f) ? v1 : pa * v1;
                *(float2*)(dst + col) = make_float2(v0, v1);
            }
        }
}

// ---------------------------------------------------------------------------
// fused inp prep + W prep (merged grids)
// ---------------------------------------------------------------------------
static constexpr int NIB = NB * NTT * ND / 4 / 256;   // 12288

__global__ __launch_bounds__(256)
void fuse_inp(const float* __restrict__ src, const float* __restrict__ W,
              const float* __restrict__ bo, const float* __restrict__ bsp)
{
    __shared__ float red[8];
    if (blockIdx.x >= NIB) {
        const int n = blockIdx.x - NIB;
        const int tid = threadIdx.x;
        float sum = 0.f;
        #pragma unroll
        for (int k0 = 0; k0 < NK3; k0 += 1024) {
            const int k = k0 + tid * 4;
            float4 v = *(const float4*)(W + (size_t)n * NK3 + k);
            ((__half2*)(g_w_h + (size_t)n * NK3 + k))[0] = __floats2half2_rn(v.x, v.y);
            ((__half2*)(g_w_h + (size_t)n * NK3 + k))[1] = __floats2half2_rn(v.z, v.w);
            if (k < ND) sum += (v.x + v.y) + (v.z + v.w);
        }
        #pragma unroll
        for (int o = 16; o; o >>= 1) sum += __shfl_xor_sync(0xffffffffu, sum, o);
        if ((tid & 31) == 0) red[tid >> 5] = sum;
        __syncthreads();
        if (tid == 0) {
            float t = ((red[0] + red[1]) + (red[2] + red[3])) +
                      ((red[4] + red[5]) + (red[6] + red[7]));
            g_bias2[n] = __ldg(bsp) * t + __ldg(bo + n);
        }
        return;
    }
    const size_t i = (size_t)blockIdx.x * 256 + threadIdx.x;
    float4 v = ((const float4*)src)[i];
    __nv_bfloat16 h0 = __float2bfloat16(v.x), h1 = __float2bfloat16(v.y);
    __nv_bfloat16 h2 = __float2bfloat16(v.z), h3 = __float2bfloat16(v.w);
    __nv_bfloat16 l0 = __float2bfloat16(v.x - __bfloat162float(h0));
    __nv_bfloat16 l1 = __float2bfloat16(v.y - __bfloat162float(h1));
    __nv_bfloat16 l2 = __float2bfloat16(v.z - __bfloat162float(h2));
    __nv_bfloat16 l3 = __float2bfloat16(v.w - __bfloat162float(h3));
    ((__nv_bfloat162*)g_inp_hi)[2 * i]     = __halves2bfloat162(h0, h1);
    ((__nv_bfloat162*)g_inp_hi)[2 * i + 1] = __halves2bfloat162(h2, h3);
    ((__nv_bfloat162*)g_inp_lo)[2 * i]     = __halves2bfloat162(l0, l1);
    ((__nv_bfloat162*)g_inp_lo)[2 * i + 1] = __halves2bfloat162(l2, l3);
    ((__half2*)g_inp_h)[2 * i]     = __floats2half2_rn(v.x, v.y);
    ((__half2*)g_inp_h)[2 * i + 1] = __floats2half2_rn(v.z, v.w);
}

// ---------------------------------------------------------------------------
// fused ctx prep (vectorized): 64s x 64d tile per block.
// NO gridsync: independent of fuse_inp (disjoint reads/writes), so under PDL
// it overlaps fuse_inp. Downstream g1_gemm's gridsync still waits for ALL
// prior grids in stream order, so correctness is preserved.
// ---------------------------------------------------------------------------
__global__ __launch_bounds__(256)
void fuse_ctx(const float* __restrict__ ctx)
{
    __shared__ float ts[64][65];
    const int b = blockIdx.z;
    const int d0 = blockIdx.x * 64;
    const int s0 = blockIdx.y * 64;
    const int tx = threadIdx.x, ty = threadIdx.y;   // 32 x 8
    #pragma unroll
    for (int r = ty; r < 64; r += 8) {
        const float2 v = *(const float2*)(ctx + (size_t)b * NSS * ND
                                          + (size_t)(s0 + r) * ND + d0 + 2 * tx);
        ts[r][2 * tx]     = v.x;
        ts[r][2 * tx + 1] = v.y;
        __nv_bfloat16 h0 = __float2bfloat16(v.x);
        __nv_bfloat16 h1 = __float2bfloat16(v.y);
        __nv_bfloat16 l0 = __float2bfloat16(v.x - __bfloat162float(h0));
        __nv_bfloat16 l1 = __float2bfloat16(v.y - __bfloat162float(h1));
        const size_t o = ((size_t)b * NSS + s0 + r) * ND + d0 + 2 * tx;
        *(__nv_bfloat162*)(g_ctx_hi + o) = __halves2bfloat162(h0, h1);
        *(__nv_bfloat162*)(g_ctx_lo + o) = __halves2bfloat162(l0, l1);
    }
    __syncthreads();
    #pragma unroll
    for (int r = ty; r < 64; r += 8) {
        float v0 = ts[2 * tx][r];
        float v1 = ts[2 * tx + 1][r];
        const size_t o = (size_t)b * ND * NSS + (size_t)(d0 + r) * NSS + s0 + 2 * tx;
        *(__half2*)(g_ctxT_h + o) = __floats2half2_rn(v0, v1);
    }
}

// ---------------------------------------------------------------------------
// row softmax over S: reads fp32 logits, writes fp16 av (fast exp)
// ---------------------------------------------------------------------------
__global__ __launch_bounds__(256)
void softmax_k()
{
    cudaGridDependencySynchronize();
    const float* row = g_scores + (size_t)blockIdx.x * NSS;
    const int tid = threadIdx.x;
    const unsigned FULL = 0xffffffffu;
    float4 x = *(const float4*)(row + tid * 4);
    float m = fmaxf(fmaxf(x.x, x.y), fmaxf(x.z, x.w));
    __shared__ float sred[8];
    __shared__ float sred2[8];
    #pragma unroll
    for (int o = 16; o; o >>= 1) m = fmaxf(m, __shfl_xor_sync(FULL, m, o));
    if ((tid & 31) == 0) sred[tid >> 5] = m;
    __syncthreads();
    m = fmaxf(fmaxf(fmaxf(sred[0], sred[1]), fmaxf(sred[2], sred[3])),
              fmaxf(fmaxf(sred[4], sred[5]), fmaxf(sred[6], sred[7])));
    float e0 = __expf(x.x - m), e1 = __expf(x.y - m);
    float e2 = __expf(x.z - m), e3 = __expf(x.w - m);
    float s = (e0 + e1) + (e2 + e3);
    #pragma unroll
    for (int o = 16; o; o >>= 1) s += __shfl_xor_sync(FULL, s, o);
    if ((tid & 31) == 0) sred2[tid >> 5] = s;
    __syncthreads();
    s = ((sred2[0] + sred2[1]) + (sred2[2] + sred2[3])) +
        ((sred2[4] + sred2[5]) + (sred2[6] + sred2[7]));
    const float inv = 1.0f / s;
    __half* dst = g_av_h + (size_t)blockIdx.x * NSS + tid * 4;
    *(__half2*)(dst)     = __floats2half2_rn(e0 * inv, e1 * inv);
    *(__half2*)(dst + 2) = __floats2half2_rn(e2 * inv, e3 * inv);
}

// ---------------------------------------------------------------------------
// gate, phase 1: partial column sums over 128-row chunks (fp16 input)
// ---------------------------------------------------------------------------
__global__ __launch_bounds__(256)
void gate_part()
{
    cudaGridDependencySynchronize();
    const int s2 = blockIdx.x * 512 + threadIdx.x * 2;
    const int tc = blockIdx.y;
    const int b = blockIdx.z;
    const __half* p = g_av_h + (size_t)b * NTT * NSS + (size_t)tc * 128 * NSS + s2;
    float2 a0 = {0.f, 0.f}, a1 = {0.f, 0.f}, a2 = {0.f, 0.f}, a3 = {0.f, 0.f};
    #pragma unroll
    for (int t = 0; t < 128; t += 4) {
        float2 f0 = __half22float2(*(const __half2*)(p + (size_t)(t + 0) * NSS));
        float2 f1 = __half22float2(*(const __half2*)(p + (size_t)(t + 1) * NSS));
        float2 f2 = __half22float2(*(const __half2*)(p + (size_t)(t + 2) * NSS));
        float2 f3 = __half22float2(*(const __half2*)(p + (size_t)(t + 3) * NSS));
        a0.x += f0.x; a0.y += f0.y;
        a1.x += f1.x; a1.y += f1.y;
        a2.x += f2.x; a2.y += f2.y;
        a3.x += f3.x; a3.y += f3.y;
    }
    float2 r;
    r.x = (a0.x + a1.x) + (a2.x + a3.x);
    r.y = (a0.y + a1.y) + (a2.y + a3.y);
    *(float2*)(&g_gpart[tc][b * NSS + s2]) = r;
}

// gate, phase 2: reduce 8 partials + sigmoid
__global__ __launch_bounds__(256)
void gate_fin()
{
    cudaGridDependencySynchronize();
    const int gid = blockIdx.x * 256 + threadIdx.x;
    float s = 0.f;
    #pragma unroll
    for (int i = 0; i < 8; ++i) s += g_gpart[i][gid];
    g_gate[gid] = 1.0f / (1.0f + __expf(-s));
}

// ---------------------------------------------------------------------------
// av_g: reads fp16 av; out2 [T,B,S] = av*gate/1024 (fp32);
//       g_avg_h [B,T,S] = fp16(av*gate)
// ---------------------------------------------------------------------------
__global__ __launch_bounds__(256)
void avg_k(float* __restrict__ out2)
{
    cudaGridDependencySynchronize();
    const int bt = blockIdx.x;
    const int b = bt >> 10, t = bt & 1023;
    const int s = threadIdx.x * 4;
    const __half* src = g_av_h + (size_t)bt * NSS + s;
    float2 f01 = __half22float2(*(const __half2*)(src));
    float2 f23 = __half22float2(*(const __half2*)(src + 2));
    float4 g = *(const float4*)(g_gate + b * NSS + s);
    float4 v;
    v.x = f01.x * g.x; v.y = f01.y * g.y; v.z = f23.x * g.z; v.w = f23.y * g.w;
    const float pool = 1.0f / 1024.0f;
    *(float4*)(out2 + ((size_t)t * NB + b) * NSS + s) =
        make_float4(v.x * pool, v.y * pool, v.z * pool, v.w * pool);
    __half2* ph = (__half2*)(g_avg_h + (size_t)bt * NSS + s);
    ph[0] = __floats2half2_rn(v.x, v.y);
    ph[1] = __floats2half2_rn(v.z, v.w);
}

// ---------------------------------------------------------------------------
// PDL launch helper: programmatic stream serialization on the legacy stream
// ---------------------------------------------------------------------------
#define LAUNCH_PDL(kern, grid, block, smem, ...) do {                         \
    cudaLaunchConfig_t _cfg = {};                                             \
    cudaLaunchAttribute _at[1];                                               \
    _at[0].id = cudaLaunchAttributeProgrammaticStreamSerialization;           \
    _at[0].val.programmaticStreamSerializationAllowed = 1;                    \
    _cfg.gridDim = grid; _cfg.blockDim = block;                               \
    _cfg.dynamicSmemBytes = smem; _cfg.stream = 0;                            \
    _cfg.attrs = _at; _cfg.numAttrs = 1;                                      \
    cudaLaunchKernelEx(&_cfg, kern, ##__VA_ARGS__);                           \
} while (0)

extern "C" void kernel_launch(void* const* d_in, const int* in_sizes, int n_in,
                              void* d_out, int out_size)
{
    const float* inp = (const float*)d_in[0];   // [B,T,768]
    const float* ctx = (const float*)d_in[1];   // [B,S,768]
    const float* W   = (const float*)d_in[2];   // [768,1536]
    const float* bo  = (const float*)d_in[3];   // [768]
    const float* ws  = (const float*)d_in[4];   // [1]
    const float* bs  = (const float*)d_in[5];   // [1]
    const float* pa  = (const float*)d_in[6];   // [1]
    float* out1 = (float*)d_out;                          // attn_h^T [T,B,768]
    float* out2 = out1 + (size_t)NTT * NB * ND;           // av_g^T   [T,B,S]

    cudaFuncSetAttribute(g1_gemm, cudaFuncAttributeMaxDynamicSharedMemorySize, SMEM_G1);
    cudaFuncSetAttribute(g2_gemm, cudaFuncAttributeMaxDynamicSharedMemorySize, SMEM_1T);
    cudaFuncSetAttribute(g3_gemm, cudaFuncAttributeMaxDynamicSharedMemorySize, SMEM_1T);

    fuse_inp<<<NIB + ND, 256>>>(inp, W, bo, bs);
    LAUNCH_PDL(fuse_ctx, dim3(ND / 64, NSS / 64, NB), dim3(32, 8), 0, ctx);
    LAUNCH_PDL(g1_gemm, dim3(8, 8, NB), dim3(256), SMEM_G1);
    LAUNCH_PDL(softmax_k, dim3(NB * NTT), dim3(256), 0);
    LAUNCH_PDL(gate_part, dim3(2, 8, NB), dim3(256), 0);
    LAUNCH_PDL(gate_fin, dim3(NB * NSS / 256), dim3(256), 0);
    LAUNCH_PDL(avg_k, dim3(NB * NTT), dim3(256), 0, out2);
    LAUNCH_PDL(g2_gemm, dim3(6, 8, NB), dim3(256), SMEM_1T, ws);
    LAUNCH_PDL(g3_gemm, dim3(6, 128, 1), dim3(256), SMEM_1T, pa, out1);
}